// round 11
// baseline (speedup 1.0000x reference)
#include <cuda_runtime.h>
#include <cstdint>

// ---------------- problem constants ----------------
#define T_LEN 4096
#define D_DIM 2048
#define H_N   6
#define DKDIM 256
#define DVDIM 512
#define KD    1536   // H_N*DKDIM
#define VD    3072   // H_N*DVDIM
#define GENW  256
#define KSZ   4

// ---------------- scratch (static device, allocation-free) ----------------
__device__ float g_q[(size_t)T_LEN*KD];
__device__ float g_k[(size_t)T_LEN*KD];
__device__ float g_x[(size_t)T_LEN*VD];      // x = h@Wv; later reused as y (permuted tf32)
__device__ float g_v[(size_t)T_LEN*VD];      // conv+silu output
__device__ float g_dyn1[(size_t)T_LEN*GENW];
__device__ float g_gate[(size_t)T_LEN*VD];
__device__ float g_o[(size_t)T_LEN*VD];      // scan output
__device__ float4 g_scal[(size_t)T_LEN*H_N]; // packed {eg, beta, qk, -} per (t,head)

// tf32-rounded, k-permuted GEMM operands (weights also transposed to [N,K])
__device__ float g_hr [(size_t)T_LEN*D_DIM];
__device__ float g_wqr[(size_t)KD*D_DIM];
__device__ float g_wkr[(size_t)KD*D_DIM];
__device__ float g_wvr[(size_t)VD*D_DIM];
__device__ float g_wgr[(size_t)VD*D_DIM];
__device__ float g_g1r[(size_t)GENW*D_DIM];
__device__ float g_wor[(size_t)D_DIM*VD];

__device__ __forceinline__ float siluf(float x) { return x / (1.0f + expf(-x)); }

__device__ __forceinline__ float f2tf32f(float x) {
    uint32_t u;
    asm("cvt.rna.tf32.f32 %0, %1;" : "=r"(u) : "f"(x));
    return __uint_as_float(u);
}
__device__ __forceinline__ uint32_t smem_u32(const void* p) {
    uint32_t a;
    asm("{ .reg .u64 t; cvta.to.shared.u64 t, %1; cvt.u32.u64 %0, t; }" : "=r"(a) : "l"(p));
    return a;
}
__device__ __forceinline__ void cp16s(uint32_t sa, const void* g) {
    asm volatile("cp.async.cg.shared.global [%0], [%1], 16;" :: "r"(sa), "l"(g) : "memory");
}

// ---------------- prep: tf32 round + k-permute (+ weight transpose) ----------------
// Layout: within each 16-wide k group, element k stored at pos (k%4)*4 + k/4.
__global__ __launch_bounds__(256)
void prep_kernel(const float* __restrict__ h,
                 const float* __restrict__ wq, const float* __restrict__ wk,
                 const float* __restrict__ wv, const float* __restrict__ wg,
                 const float* __restrict__ g1, const float* __restrict__ wo,
                 float* __restrict__ hr,
                 float* __restrict__ wqr, float* __restrict__ wkr,
                 float* __restrict__ wvr, float* __restrict__ wgr,
                 float* __restrict__ g1r, float* __restrict__ wor) {
    int b = blockIdx.x;
    if (b < 2048) {          // h: round + permute, one 16-group per thread
        size_t e0 = ((size_t)b * 256 + threadIdx.x) * 16;
        float4 r0 = *(const float4*)(h + e0);
        float4 r1 = *(const float4*)(h + e0 + 4);
        float4 r2 = *(const float4*)(h + e0 + 8);
        float4 r3 = *(const float4*)(h + e0 + 12);
        float4 o0 = make_float4(f2tf32f(r0.x), f2tf32f(r1.x), f2tf32f(r2.x), f2tf32f(r3.x));
        float4 o1 = make_float4(f2tf32f(r0.y), f2tf32f(r1.y), f2tf32f(r2.y), f2tf32f(r3.y));
        float4 o2 = make_float4(f2tf32f(r0.z), f2tf32f(r1.z), f2tf32f(r2.z), f2tf32f(r3.z));
        float4 o3 = make_float4(f2tf32f(r0.w), f2tf32f(r1.w), f2tf32f(r2.w), f2tf32f(r3.w));
        *(float4*)(hr + e0)      = o0;
        *(float4*)(hr + e0 + 4)  = o1;
        *(float4*)(hr + e0 + 8)  = o2;
        *(float4*)(hr + e0 + 12) = o3;
        return;
    }
    b -= 2048;
    const float* W; float* O; int K, N;
    if (b < 768)                 { W = wq; O = wqr; K = D_DIM; N = KD; }
    else if ((b -= 768) < 768)   { W = wk; O = wkr; K = D_DIM; N = KD; }
    else if ((b -= 768) < 1536)  { W = wv; O = wvr; K = D_DIM; N = VD; }
    else if ((b -= 1536) < 1536) { W = wg; O = wgr; K = D_DIM; N = VD; }
    else if ((b -= 1536) < 128)  { W = g1; O = g1r; K = D_DIM; N = GENW; }
    else                         { b -= 128; W = wo; O = wor; K = VD; N = D_DIM; }
    int ntx = N >> 6;
    int tn = b % ntx, tk = b / ntx;
    int kb = tk * 64, nb = tn * 64;
    __shared__ float tile[64][65];
    int c = threadIdx.x & 63, r0i = threadIdx.x >> 6;
    #pragma unroll
    for (int i = 0; i < 16; i++) {
        int r = r0i + i * 4;
        tile[r][c] = W[(size_t)(kb + r) * N + nb + c];
    }
    __syncthreads();
    int nl = threadIdx.x >> 2, grp = threadIdx.x & 3;
    float* orow = O + (size_t)(nb + nl) * K + kb + grp * 16;
    #pragma unroll
    for (int a = 0; a < 4; a++) {
        float4 o;
        o.x = f2tf32f(tile[grp*16 + a     ][nl]);
        o.y = f2tf32f(tile[grp*16 + a + 4 ][nl]);
        o.z = f2tf32f(tile[grp*16 + a + 8 ][nl]);
        o.w = f2tf32f(tile[grp*16 + a + 12][nl]);
        *(float4*)(orow + a * 4) = o;
    }
}

// ---------------- tf32 GEMM body (permuted operands, LDS.128 frags) ----------------
// BK=16, 4-stage cp.async ring (64KB dyn smem), 256 threads, 2 CTAs/SM. (R6 config)
#define GEMM_SMEM 65536

__device__ __forceinline__ void gemm_body(
    const float* __restrict__ A, const float* __restrict__ B, float* __restrict__ C,
    int K, int Ns, int row0, int col0, int act)
{
    extern __shared__ float sm[];          // 4 stages x 4096 floats (A 2048 | B 2048)
    const int tid  = threadIdx.x;
    const int warp = tid >> 5, lane = tid & 31;
    const int gid  = lane >> 2, tig = lane & 3;
    const int wm   = warp >> 1, wn = warp & 1;
    const int KT   = K >> 4;
    const uint32_t smb = smem_u32(sm);

    float acc[2][8][4];
    #pragma unroll
    for (int i = 0; i < 2; i++)
        #pragma unroll
        for (int j = 0; j < 8; j++)
            #pragma unroll
            for (int cc = 0; cc < 4; cc++) acc[i][j][cc] = 0.0f;

    const int rA = tid >> 2,        cA = (tid & 3) * 4;
    const float* Abase = A + (size_t)(row0 + rA) * K + cA;
    const float* Bbase = B + (size_t)(col0 + rA) * K + cA;

    auto issue = [&](int kt) {
        if (kt < KT) {
            uint32_t so = smb + (uint32_t)(kt & 3) * 16384u + (uint32_t)(rA * 16 + cA) * 4u;
            int k0 = kt << 4;
            cp16s(so,                 Abase + k0);
            cp16s(so + 4096,          Abase + k0 + (size_t)64 * K);
            cp16s(so + 8192,          Bbase + k0);
            cp16s(so + 8192 + 4096,   Bbase + k0 + (size_t)64 * K);
        }
        asm volatile("cp.async.commit_group;" ::: "memory");
    };

    issue(0); issue(1); issue(2);
    for (int kt = 0; kt < KT; ++kt) {
        asm volatile("cp.async.wait_group 2;" ::: "memory");
        __syncthreads();
        issue(kt + 3);

        const float* As = sm + (kt & 3) * 4096;
        const float* Bs = As + 2048;

        float4 A0[2], A1[2];
        #pragma unroll
        for (int i = 0; i < 2; i++) {
            int m = wm * 32 + i * 16 + gid;
            A0[i] = *(const float4*)(As + m * 16 + tig * 4);
            A1[i] = *(const float4*)(As + (m + 8) * 16 + tig * 4);
        }
        #pragma unroll
        for (int jh = 0; jh < 2; jh++) {
            float4 Bv[4];
            #pragma unroll
            for (int j = 0; j < 4; j++) {
                int n = wn * 64 + (jh * 4 + j) * 8 + gid;
                Bv[j] = *(const float4*)(Bs + n * 16 + tig * 4);
            }
            #pragma unroll
            for (int i = 0; i < 2; i++)
                #pragma unroll
                for (int j = 0; j < 4; j++) {
                    float* ac = acc[i][jh * 4 + j];
                    asm volatile(
                        "mma.sync.aligned.m16n8k8.row.col.f32.tf32.tf32.f32 "
                        "{%0,%1,%2,%3}, {%4,%5,%6,%7}, {%8,%9}, {%0,%1,%2,%3};"
                        : "+f"(ac[0]), "+f"(ac[1]), "+f"(ac[2]), "+f"(ac[3])
                        : "r"(__float_as_uint(A0[i].x)), "r"(__float_as_uint(A1[i].x)),
                          "r"(__float_as_uint(A0[i].y)), "r"(__float_as_uint(A1[i].y)),
                          "r"(__float_as_uint(Bv[j].x)), "r"(__float_as_uint(Bv[j].y)));
                    asm volatile(
                        "mma.sync.aligned.m16n8k8.row.col.f32.tf32.tf32.f32 "
                        "{%0,%1,%2,%3}, {%4,%5,%6,%7}, {%8,%9}, {%0,%1,%2,%3};"
                        : "+f"(ac[0]), "+f"(ac[1]), "+f"(ac[2]), "+f"(ac[3])
                        : "r"(__float_as_uint(A0[i].z)), "r"(__float_as_uint(A1[i].z)),
                          "r"(__float_as_uint(A0[i].w)), "r"(__float_as_uint(A1[i].w)),
                          "r"(__float_as_uint(Bv[j].z)), "r"(__float_as_uint(Bv[j].w)));
                }
        }
    }

    #pragma unroll
    for (int i = 0; i < 2; ++i) {
        int row = row0 + wm * 32 + i * 16 + gid;
        #pragma unroll
        for (int j = 0; j < 8; ++j) {
            int col = col0 + wn * 64 + j * 8 + 2 * tig;
            float v0 = acc[i][j][0], v1 = acc[i][j][1];
            float v2 = acc[i][j][2], v3 = acc[i][j][3];
            if (act) { v0 = siluf(v0); v1 = siluf(v1); v2 = siluf(v2); v3 = siluf(v3); }
            *(float2*)(C + (size_t)row * Ns + col)       = make_float2(v0, v1);
            *(float2*)(C + (size_t)(row + 8) * Ns + col) = make_float2(v2, v3);
        }
    }
}

// fused projections q|k|x|gate|dyn1 (74 column tiles, single launch)
__global__ __launch_bounds__(256, 2)
void proj_gemm_kernel(const float* __restrict__ hR,
                      const float* __restrict__ WqR, const float* __restrict__ WkR,
                      const float* __restrict__ WvR, const float* __restrict__ WgR,
                      const float* __restrict__ g1R,
                      float* __restrict__ q, float* __restrict__ k,
                      float* __restrict__ x, float* __restrict__ g,
                      float* __restrict__ d1) {
    const int by = blockIdx.y;
    const float* B; float* C; int Ns, col0, act;
    if (by < 12)      { B = WqR; C = q;  Ns = KD;   col0 = by * 128;        act = 1; }
    else if (by < 24) { B = WkR; C = k;  Ns = KD;   col0 = (by - 12) * 128; act = 1; }
    else if (by < 48) { B = WvR; C = x;  Ns = VD;   col0 = (by - 24) * 128; act = 0; }
    else if (by < 72) { B = WgR; C = g;  Ns = VD;   col0 = (by - 48) * 128; act = 0; }
    else              { B = g1R; C = d1; Ns = GENW; col0 = (by - 72) * 128; act = 1; }
    gemm_body(hR, B, C, D_DIM, Ns, blockIdx.x * 128, col0, act);
}

__global__ __launch_bounds__(256, 2)
void wo_gemm_kernel(const float* __restrict__ yR, const float* __restrict__ WoR,
                    float* __restrict__ out) {
    gemm_body(yR, WoR, out, VD, D_DIM, blockIdx.x * 128, blockIdx.y * 128, 0);
}

// ---------------- fused per-token post: l2qk + dyn + betag + conv -------------------
// Writes packed scal[t*6+h] = {eg, beta, qk, -} for the scan.
__global__ __launch_bounds__(256)
void fused_post_kernel(const float* __restrict__ h,
                       const float* __restrict__ Wb, const float* __restrict__ Wa,
                       const float* __restrict__ A_log, const float* __restrict__ dt_bias,
                       float* __restrict__ q, float* __restrict__ k,
                       const float* __restrict__ dyn1, const float* __restrict__ w2,
                       const float* __restrict__ cw,
                       const float* __restrict__ x, float* __restrict__ v,
                       float* __restrict__ scal) {
    const int t = blockIdx.x;
    const int tid = threadIdx.x, wid = tid >> 5, lane = tid & 31;
    __shared__ float sdyn[4];
    __shared__ float red[8][12];

    if (wid < 6) {
        int vec = t * 6 + wid;
        float* qr = q + (size_t)vec * DKDIM;
        float* kr = k + (size_t)vec * DKDIM;
        float xq[8], xk[8];
        float sq = 0.f, sk = 0.f, sx = 0.f;
        #pragma unroll
        for (int i = 0; i < 8; i++) {
            xq[i] = qr[lane + 32*i]; xk[i] = kr[lane + 32*i];
            sq += xq[i]*xq[i]; sk += xk[i]*xk[i]; sx += xq[i]*xk[i];
        }
        #pragma unroll
        for (int off = 16; off; off >>= 1) {
            sq += __shfl_xor_sync(0xffffffffu, sq, off);
            sk += __shfl_xor_sync(0xffffffffu, sk, off);
            sx += __shfl_xor_sync(0xffffffffu, sx, off);
        }
        float rq = rsqrtf(sq + 1e-6f) * 0.0625f;   // fold DK^-0.5 into q
        float rk = rsqrtf(sk + 1e-6f);
        #pragma unroll
        for (int i = 0; i < 8; i++) {
            qr[lane + 32*i] = xq[i] * rq;
            kr[lane + 32*i] = xk[i] * rk;
        }
        if (lane == 0) scal[(size_t)vec * 4 + 2] = sx * rq * rk;   // qk
    } else if (wid == 6) {
        const float* r = dyn1 + (size_t)t * GENW;
        float a0 = 0.f, a1 = 0.f, a2 = 0.f, a3 = 0.f;
        #pragma unroll
        for (int i = 0; i < 8; i++) {
            int d = lane + 32*i;
            float vv = r[d];
            const float* w = w2 + d*4;
            a0 += vv*w[0]; a1 += vv*w[1]; a2 += vv*w[2]; a3 += vv*w[3];
        }
        #pragma unroll
        for (int off = 16; off; off >>= 1) {
            a0 += __shfl_xor_sync(0xffffffffu, a0, off);
            a1 += __shfl_xor_sync(0xffffffffu, a1, off);
            a2 += __shfl_xor_sync(0xffffffffu, a2, off);
            a3 += __shfl_xor_sync(0xffffffffu, a3, off);
        }
        if (lane == 0) { sdyn[0]=a0; sdyn[1]=a1; sdyn[2]=a2; sdyn[3]=a3; }
    }
    __syncthreads();

    const float* hr = h + (size_t)t * D_DIM;
    float acc[12];
    #pragma unroll
    for (int j = 0; j < 12; j++) acc[j] = 0.f;
    for (int d = tid; d < D_DIM; d += 256) {
        float hv = hr[d];
        const float* wb = Wb + d*6;
        const float* wa = Wa + d*6;
        #pragma unroll
        for (int j = 0; j < 6; j++) {
            acc[j]   += hv * wb[j];
            acc[6+j] += hv * wa[j];
        }
    }
    #pragma unroll
    for (int j = 0; j < 12; j++)
        #pragma unroll
        for (int off = 16; off; off >>= 1)
            acc[j] += __shfl_xor_sync(0xffffffffu, acc[j], off);
    if (lane == 0) {
        #pragma unroll
        for (int j = 0; j < 12; j++) red[wid][j] = acc[j];
    }
    __syncthreads();
    if (tid < 12) {
        float s = 0.f;
        #pragma unroll
        for (int i = 0; i < 8; i++) s += red[i][tid];
        if (tid < 6) {
            scal[(size_t)(t*6 + tid) * 4 + 1] = 1.0f / (1.0f + expf(-s));   // beta
        } else {
            int hh = tid - 6;
            float xx = s + dt_bias[hh];
            float sp = (xx > 20.0f) ? xx : log1pf(expf(xx));
            scal[(size_t)(t*6 + hh) * 4 + 0] = expf(-expf(A_log[hh]) * sp); // eg
        }
    }

    float dd[4];
    #pragma unroll
    for (int j = 0; j < 4; j++) dd[j] = sdyn[j];
    #pragma unroll
    for (int gi = 0; gi < 3; gi++) {
        int c = gi * 1024 + tid * 4;
        float a0 = 0.f, a1 = 0.f, a2 = 0.f, a3 = 0.f;
        #pragma unroll
        for (int j = 0; j < 4; j++) {
            int tt = t + j - 3;
            if (tt >= 0) {
                float4 xv = *(const float4*)(x + (size_t)tt * VD + c);
                a0 += (cw[(c+0)*4 + j] + dd[j]) * xv.x;
                a1 += (cw[(c+1)*4 + j] + dd[j]) * xv.y;
                a2 += (cw[(c+2)*4 + j] + dd[j]) * xv.z;
                a3 += (cw[(c+3)*4 + j] + dd[j]) * xv.w;
            }
        }
        float4 rr;
        rr.x = siluf(a0); rr.y = siluf(a1); rr.z = siluf(a2); rr.w = siluf(a3);
        *(float4*)(v + (size_t)t * VD + c) = rr;
    }
}

// ---------------- gated delta-rule scan: 2 cols/warp, 1-warp blocks ----------------
// 1536 blocks x 32 threads: finest scheduling granularity -> best inter-SM balance.
// Register double-buffered; packed scalar load (1 LDG.128); no synchronization.
__global__ __launch_bounds__(32)
void scan_kernel(const float* __restrict__ q, const float* __restrict__ k,
                 const float* __restrict__ v, const float4* __restrict__ scal,
                 float* __restrict__ o) {
    const int warpg = blockIdx.x;             // 0..1535
    const int c0    = warpg * 2;
    const int head  = c0 >> 9;
    const int lane  = threadIdx.x & 31;

    const float* qb = q + head * DKDIM + lane;
    const float* kb = k + head * DKDIM + lane;

    float s0[8], s1[8];
    #pragma unroll
    for (int i = 0; i < 8; i++) { s0[i] = 0.f; s1[i] = 0.f; }

    float qA[8], kA[8]; float2 vA; float4 scA;
    float qB[8], kB[8]; float2 vB; float4 scB;

    #define SCAN_LOAD(t, qr, kr, vv, sc) do {                          \
        size_t _off = (size_t)(t) * KD;                                \
        _Pragma("unroll")                                              \
        for (int _i = 0; _i < 8; _i++) {                               \
            qr[_i] = qb[_off + 32*_i];                                 \
            kr[_i] = kb[_off + 32*_i];                                 \
        }                                                              \
        vv = *(const float2*)(v + (size_t)(t) * VD + c0);              \
        sc = scal[(t)*6 + head];                                       \
    } while (0)

    #define SCAN_STEP(t, qr, kr, vv, sc) do {                          \
        float eb = sc.x, bt = sc.y, qv = sc.z;                         \
        float d0 = 0.f, d1 = 0.f, p0 = 0.f, p1 = 0.f;                  \
        _Pragma("unroll")                                              \
        for (int _i = 0; _i < 8; _i++) {                               \
            float t0 = s0[_i] * eb, t1 = s1[_i] * eb;                  \
            s0[_i] = t0; s1[_i] = t1;                                  \
            d0 += kr[_i] * t0; d1 += kr[_i] * t1;                      \
            p0 += qr[_i] * t0; p1 += qr[_i] * t1;                      \
        }                                                              \
        _Pragma("unroll")                                              \
        for (int _off = 16; _off; _off >>= 1) {                        \
            d0 += __shfl_xor_sync(0xffffffffu, d0, _off);              \
            d1 += __shfl_xor_sync(0xffffffffu, d1, _off);              \
            p0 += __shfl_xor_sync(0xffffffffu, p0, _off);              \
            p1 += __shfl_xor_sync(0xffffffffu, p1, _off);              \
        }                                                              \
        float dv0 = (vv.x - d0) * bt, dv1 = (vv.y - d1) * bt;          \
        _Pragma("unroll")                                              \
        for (int _i = 0; _i < 8; _i++) {                               \
            s0[_i] += kr[_i] * dv0; s1[_i] += kr[_i] * dv1;            \
        }                                                              \
        if (lane == 0) {                                               \
            *(float2*)(o + (size_t)(t) * VD + c0) =                    \
                make_float2(p0 + qv * dv0, p1 + qv * dv1);             \
        }                                                              \
    } while (0)

    SCAN_LOAD(0, qA, kA, vA, scA);
    for (int t = 0; t < T_LEN; t += 2) {
        SCAN_LOAD(t + 1, qB, kB, vB, scB);
        SCAN_STEP(t, qA, kA, vA, scA);
        if (t + 2 < T_LEN) SCAN_LOAD(t + 2, qA, kA, vA, scA);
        SCAN_STEP(t + 1, qB, kB, vB, scB);
    }
    #undef SCAN_LOAD
    #undef SCAN_STEP
}

// ---------------- gated RMSNorm -> tf32-rounded, k-permuted y ----------------
__global__ __launch_bounds__(128)
void rmsnorm_gate_kernel(const float* __restrict__ o, const float* __restrict__ gate,
                         const float* __restrict__ nw, float* __restrict__ y) {
    int row = blockIdx.x;                  // t*6 + h
    int tid = threadIdx.x;
    size_t base = (size_t)(row / 6) * VD + (size_t)(row % 6) * DVDIM;
    int g = tid >> 2, a = tid & 3;

    float ov[4], gv[4], nv[4];
    float ss = 0.f;
    #pragma unroll
    for (int i = 0; i < 4; i++) {
        int c = g * 16 + a + 4 * i;
        ov[i] = o[base + c];
        gv[i] = gate[base + c];
        nv[i] = nw[c];
        ss += ov[i] * ov[i];
    }
    #pragma unroll
    for (int off = 16; off; off >>= 1) ss += __shfl_xor_sync(0xffffffffu, ss, off);
    __shared__ float red[4];
    int w = tid >> 5, lane = tid & 31;
    if (lane == 0) red[w] = ss;
    __syncthreads();
    float tot = red[0] + red[1] + red[2] + red[3];
    float rms = rsqrtf(tot * (1.0f / (float)DVDIM) + 1e-5f);

    float4 r;
    r.x = f2tf32f(ov[0] * rms * nv[0] * siluf(gv[0]));
    r.y = f2tf32f(ov[1] * rms * nv[1] * siluf(gv[1]));
    r.z = f2tf32f(ov[2] * rms * nv[2] * siluf(gv[2]));
    r.w = f2tf32f(ov[3] * rms * nv[3] * siluf(gv[3]));
    *(float4*)(y + base + g * 16 + 4 * a) = r;   // k-permuted slot
}

// ---------------- launch ----------------
extern "C" void kernel_launch(void* const* d_in, const int* in_sizes, int n_in,
                              void* d_out, int out_size) {
    const float* h       = (const float*)d_in[0];
    const float* Wq      = (const float*)d_in[1];
    const float* Wk      = (const float*)d_in[2];
    const float* Wv      = (const float*)d_in[3];
    const float* Wb      = (const float*)d_in[4];
    const float* Wa      = (const float*)d_in[5];
    const float* Wg      = (const float*)d_in[6];
    const float* Wo      = (const float*)d_in[7];
    const float* A_log   = (const float*)d_in[8];
    const float* dt_bias = (const float*)d_in[9];
    const float* conv_w  = (const float*)d_in[10];
    const float* gen_w1  = (const float*)d_in[11];
    const float* gen_w2  = (const float*)d_in[12];
    const float* norm_w  = (const float*)d_in[13];
    float* out = (float*)d_out;

    float *pq, *pk, *px, *pv, *pd1, *pgate, *po;
    float4* pscal;
    float *phr, *pwqr, *pwkr, *pwvr, *pwgr, *pg1r, *pwor;
    cudaGetSymbolAddress((void**)&pq,    g_q);
    cudaGetSymbolAddress((void**)&pk,    g_k);
    cudaGetSymbolAddress((void**)&px,    g_x);
    cudaGetSymbolAddress((void**)&pv,    g_v);
    cudaGetSymbolAddress((void**)&pd1,   g_dyn1);
    cudaGetSymbolAddress((void**)&pgate, g_gate);
    cudaGetSymbolAddress((void**)&po,    g_o);
    cudaGetSymbolAddress((void**)&pscal, g_scal);
    cudaGetSymbolAddress((void**)&phr,   g_hr);
    cudaGetSymbolAddress((void**)&pwqr,  g_wqr);
    cudaGetSymbolAddress((void**)&pwkr,  g_wkr);
    cudaGetSymbolAddress((void**)&pwvr,  g_wvr);
    cudaGetSymbolAddress((void**)&pwgr,  g_wgr);
    cudaGetSymbolAddress((void**)&pg1r,  g_g1r);
    cudaGetSymbolAddress((void**)&pwor,  g_wor);

    cudaFuncSetAttribute(proj_gemm_kernel, cudaFuncAttributeMaxDynamicSharedMemorySize, GEMM_SMEM);
    cudaFuncSetAttribute(wo_gemm_kernel,   cudaFuncAttributeMaxDynamicSharedMemorySize, GEMM_SMEM);

    // (0) round + permute h, transpose + round + permute weights
    prep_kernel<<<8320, 256>>>(h, Wq, Wk, Wv, Wg, gen_w1, Wo,
                               phr, pwqr, pwkr, pwvr, pwgr, pg1r, pwor);

    // (1) fused projections q|k|x|gate|dyn1 (74 x 32 tiles)
    proj_gemm_kernel<<<dim3(T_LEN/128, 74), 256, GEMM_SMEM>>>(
        phr, pwqr, pwkr, pwvr, pwgr, pg1r, pq, pk, px, pgate, pd1);

    // (2) fused per-token post-processing (writes packed scal)
    fused_post_kernel<<<T_LEN, 256>>>(h, Wb, Wa, A_log, dt_bias,
                                      pq, pk, pd1, gen_w2, conv_w,
                                      px, pv, (float*)pscal);

    // (3) scan: 1536 one-warp blocks (ncu profiles launch index 3)
    scan_kernel<<<1536, 32>>>(pq, pk, pv, pscal, po);

    // (4) gated RMSNorm -> permuted tf32 y (reuses g_x)
    rmsnorm_gate_kernel<<<T_LEN*H_N, 128>>>(po, pgate, norm_w, px);

    // (5) out = y @ Wo
    wo_gemm_kernel<<<dim3(T_LEN/128, D_DIM/128), 256, GEMM_SMEM>>>(px, pwor, out);
}

// round 12
// speedup vs baseline: 1.2802x; 1.2802x over previous
#include <cuda_runtime.h>
#include <cstdint>

// ---------------- problem constants ----------------
#define T_LEN 4096
#define D_DIM 2048
#define H_N   6
#define DKDIM 256
#define DVDIM 512
#define KD    1536   // H_N*DKDIM
#define VD    3072   // H_N*DVDIM
#define GENW  256
#define KSZ   4

// ---------------- scratch (static device, allocation-free) ----------------
__device__ float g_q[(size_t)T_LEN*KD];
__device__ float g_k[(size_t)T_LEN*KD];
__device__ float g_x[(size_t)T_LEN*VD];      // x = h@Wv; later reused as y (permuted tf32)
__device__ float g_v[(size_t)T_LEN*VD];      // conv+silu output
__device__ float g_dyn1[(size_t)T_LEN*GENW];
__device__ float g_gate[(size_t)T_LEN*VD];
__device__ float g_o[(size_t)T_LEN*VD];      // scan output
__device__ float4 g_scal[(size_t)T_LEN*H_N]; // packed {eg, beta, qk, -} per (t,head)

// tf32-rounded, k-permuted GEMM operands (weights also transposed to [N,K])
__device__ float g_hr [(size_t)T_LEN*D_DIM];
__device__ float g_wqr[(size_t)KD*D_DIM];
__device__ float g_wkr[(size_t)KD*D_DIM];
__device__ float g_wvr[(size_t)VD*D_DIM];
__device__ float g_wgr[(size_t)VD*D_DIM];
__device__ float g_g1r[(size_t)GENW*D_DIM];
__device__ float g_wor[(size_t)D_DIM*VD];

__device__ __forceinline__ float siluf(float x) { return x / (1.0f + expf(-x)); }

__device__ __forceinline__ float f2tf32f(float x) {
    uint32_t u;
    asm("cvt.rna.tf32.f32 %0, %1;" : "=r"(u) : "f"(x));
    return __uint_as_float(u);
}
__device__ __forceinline__ uint32_t smem_u32(const void* p) {
    uint32_t a;
    asm("{ .reg .u64 t; cvta.to.shared.u64 t, %1; cvt.u32.u64 %0, t; }" : "=r"(a) : "l"(p));
    return a;
}
__device__ __forceinline__ void cp16s(uint32_t sa, const void* g) {
    asm volatile("cp.async.cg.shared.global [%0], [%1], 16;" :: "r"(sa), "l"(g) : "memory");
}

// ---------------- prep: tf32 round + k-permute (+ weight transpose) ----------------
// Layout: within each 16-wide k group, element k stored at pos (k%4)*4 + k/4.
__global__ __launch_bounds__(256)
void prep_kernel(const float* __restrict__ h,
                 const float* __restrict__ wq, const float* __restrict__ wk,
                 const float* __restrict__ wv, const float* __restrict__ wg,
                 const float* __restrict__ g1, const float* __restrict__ wo,
                 float* __restrict__ hr,
                 float* __restrict__ wqr, float* __restrict__ wkr,
                 float* __restrict__ wvr, float* __restrict__ wgr,
                 float* __restrict__ g1r, float* __restrict__ wor) {
    int b = blockIdx.x;
    if (b < 2048) {          // h: round + permute, one 16-group per thread
        size_t e0 = ((size_t)b * 256 + threadIdx.x) * 16;
        float4 r0 = *(const float4*)(h + e0);
        float4 r1 = *(const float4*)(h + e0 + 4);
        float4 r2 = *(const float4*)(h + e0 + 8);
        float4 r3 = *(const float4*)(h + e0 + 12);
        float4 o0 = make_float4(f2tf32f(r0.x), f2tf32f(r1.x), f2tf32f(r2.x), f2tf32f(r3.x));
        float4 o1 = make_float4(f2tf32f(r0.y), f2tf32f(r1.y), f2tf32f(r2.y), f2tf32f(r3.y));
        float4 o2 = make_float4(f2tf32f(r0.z), f2tf32f(r1.z), f2tf32f(r2.z), f2tf32f(r3.z));
        float4 o3 = make_float4(f2tf32f(r0.w), f2tf32f(r1.w), f2tf32f(r2.w), f2tf32f(r3.w));
        *(float4*)(hr + e0)      = o0;
        *(float4*)(hr + e0 + 4)  = o1;
        *(float4*)(hr + e0 + 8)  = o2;
        *(float4*)(hr + e0 + 12) = o3;
        return;
    }
    b -= 2048;
    const float* W; float* O; int K, N;
    if (b < 768)                 { W = wq; O = wqr; K = D_DIM; N = KD; }
    else if ((b -= 768) < 768)   { W = wk; O = wkr; K = D_DIM; N = KD; }
    else if ((b -= 768) < 1536)  { W = wv; O = wvr; K = D_DIM; N = VD; }
    else if ((b -= 1536) < 1536) { W = wg; O = wgr; K = D_DIM; N = VD; }
    else if ((b -= 1536) < 128)  { W = g1; O = g1r; K = D_DIM; N = GENW; }
    else                         { b -= 128; W = wo; O = wor; K = VD; N = D_DIM; }
    int ntx = N >> 6;
    int tn = b % ntx, tk = b / ntx;
    int kb = tk * 64, nb = tn * 64;
    __shared__ float tile[64][65];
    int c = threadIdx.x & 63, r0i = threadIdx.x >> 6;
    #pragma unroll
    for (int i = 0; i < 16; i++) {
        int r = r0i + i * 4;
        tile[r][c] = W[(size_t)(kb + r) * N + nb + c];
    }
    __syncthreads();
    int nl = threadIdx.x >> 2, grp = threadIdx.x & 3;
    float* orow = O + (size_t)(nb + nl) * K + kb + grp * 16;
    #pragma unroll
    for (int a = 0; a < 4; a++) {
        float4 o;
        o.x = f2tf32f(tile[grp*16 + a     ][nl]);
        o.y = f2tf32f(tile[grp*16 + a + 4 ][nl]);
        o.z = f2tf32f(tile[grp*16 + a + 8 ][nl]);
        o.w = f2tf32f(tile[grp*16 + a + 12][nl]);
        *(float4*)(orow + a * 4) = o;
    }
}

// ---------------- tf32 GEMM body (permuted operands, LDS.128 frags) ----------------
// BK=16, 4-stage cp.async ring (64KB dyn smem), 256 threads, 2 CTAs/SM. (R6 config)
#define GEMM_SMEM 65536

__device__ __forceinline__ void gemm_body(
    const float* __restrict__ A, const float* __restrict__ B, float* __restrict__ C,
    int K, int Ns, int row0, int col0, int act)
{
    extern __shared__ float sm[];          // 4 stages x 4096 floats (A 2048 | B 2048)
    const int tid  = threadIdx.x;
    const int warp = tid >> 5, lane = tid & 31;
    const int gid  = lane >> 2, tig = lane & 3;
    const int wm   = warp >> 1, wn = warp & 1;
    const int KT   = K >> 4;
    const uint32_t smb = smem_u32(sm);

    float acc[2][8][4];
    #pragma unroll
    for (int i = 0; i < 2; i++)
        #pragma unroll
        for (int j = 0; j < 8; j++)
            #pragma unroll
            for (int cc = 0; cc < 4; cc++) acc[i][j][cc] = 0.0f;

    const int rA = tid >> 2,        cA = (tid & 3) * 4;
    const float* Abase = A + (size_t)(row0 + rA) * K + cA;
    const float* Bbase = B + (size_t)(col0 + rA) * K + cA;

    auto issue = [&](int kt) {
        if (kt < KT) {
            uint32_t so = smb + (uint32_t)(kt & 3) * 16384u + (uint32_t)(rA * 16 + cA) * 4u;
            int k0 = kt << 4;
            cp16s(so,                 Abase + k0);
            cp16s(so + 4096,          Abase + k0 + (size_t)64 * K);
            cp16s(so + 8192,          Bbase + k0);
            cp16s(so + 8192 + 4096,   Bbase + k0 + (size_t)64 * K);
        }
        asm volatile("cp.async.commit_group;" ::: "memory");
    };

    issue(0); issue(1); issue(2);
    for (int kt = 0; kt < KT; ++kt) {
        asm volatile("cp.async.wait_group 2;" ::: "memory");
        __syncthreads();
        issue(kt + 3);

        const float* As = sm + (kt & 3) * 4096;
        const float* Bs = As + 2048;

        float4 A0[2], A1[2];
        #pragma unroll
        for (int i = 0; i < 2; i++) {
            int m = wm * 32 + i * 16 + gid;
            A0[i] = *(const float4*)(As + m * 16 + tig * 4);
            A1[i] = *(const float4*)(As + (m + 8) * 16 + tig * 4);
        }
        #pragma unroll
        for (int jh = 0; jh < 2; jh++) {
            float4 Bv[4];
            #pragma unroll
            for (int j = 0; j < 4; j++) {
                int n = wn * 64 + (jh * 4 + j) * 8 + gid;
                Bv[j] = *(const float4*)(Bs + n * 16 + tig * 4);
            }
            #pragma unroll
            for (int i = 0; i < 2; i++)
                #pragma unroll
                for (int j = 0; j < 4; j++) {
                    float* ac = acc[i][jh * 4 + j];
                    asm volatile(
                        "mma.sync.aligned.m16n8k8.row.col.f32.tf32.tf32.f32 "
                        "{%0,%1,%2,%3}, {%4,%5,%6,%7}, {%8,%9}, {%0,%1,%2,%3};"
                        : "+f"(ac[0]), "+f"(ac[1]), "+f"(ac[2]), "+f"(ac[3])
                        : "r"(__float_as_uint(A0[i].x)), "r"(__float_as_uint(A1[i].x)),
                          "r"(__float_as_uint(A0[i].y)), "r"(__float_as_uint(A1[i].y)),
                          "r"(__float_as_uint(Bv[j].x)), "r"(__float_as_uint(Bv[j].y)));
                    asm volatile(
                        "mma.sync.aligned.m16n8k8.row.col.f32.tf32.tf32.f32 "
                        "{%0,%1,%2,%3}, {%4,%5,%6,%7}, {%8,%9}, {%0,%1,%2,%3};"
                        : "+f"(ac[0]), "+f"(ac[1]), "+f"(ac[2]), "+f"(ac[3])
                        : "r"(__float_as_uint(A0[i].z)), "r"(__float_as_uint(A1[i].z)),
                          "r"(__float_as_uint(A0[i].w)), "r"(__float_as_uint(A1[i].w)),
                          "r"(__float_as_uint(Bv[j].z)), "r"(__float_as_uint(Bv[j].w)));
                }
        }
    }

    #pragma unroll
    for (int i = 0; i < 2; ++i) {
        int row = row0 + wm * 32 + i * 16 + gid;
        #pragma unroll
        for (int j = 0; j < 8; ++j) {
            int col = col0 + wn * 64 + j * 8 + 2 * tig;
            float v0 = acc[i][j][0], v1 = acc[i][j][1];
            float v2 = acc[i][j][2], v3 = acc[i][j][3];
            if (act) { v0 = siluf(v0); v1 = siluf(v1); v2 = siluf(v2); v3 = siluf(v3); }
            *(float2*)(C + (size_t)row * Ns + col)       = make_float2(v0, v1);
            *(float2*)(C + (size_t)(row + 8) * Ns + col) = make_float2(v2, v3);
        }
    }
}

// fused projections q|k|x|gate|dyn1 (74 column tiles, single launch)
__global__ __launch_bounds__(256, 2)
void proj_gemm_kernel(const float* __restrict__ hR,
                      const float* __restrict__ WqR, const float* __restrict__ WkR,
                      const float* __restrict__ WvR, const float* __restrict__ WgR,
                      const float* __restrict__ g1R,
                      float* __restrict__ q, float* __restrict__ k,
                      float* __restrict__ x, float* __restrict__ g,
                      float* __restrict__ d1) {
    const int by = blockIdx.y;
    const float* B; float* C; int Ns, col0, act;
    if (by < 12)      { B = WqR; C = q;  Ns = KD;   col0 = by * 128;        act = 1; }
    else if (by < 24) { B = WkR; C = k;  Ns = KD;   col0 = (by - 12) * 128; act = 1; }
    else if (by < 48) { B = WvR; C = x;  Ns = VD;   col0 = (by - 24) * 128; act = 0; }
    else if (by < 72) { B = WgR; C = g;  Ns = VD;   col0 = (by - 48) * 128; act = 0; }
    else              { B = g1R; C = d1; Ns = GENW; col0 = (by - 72) * 128; act = 1; }
    gemm_body(hR, B, C, D_DIM, Ns, blockIdx.x * 128, col0, act);
}

__global__ __launch_bounds__(256, 2)
void wo_gemm_kernel(const float* __restrict__ yR, const float* __restrict__ WoR,
                    float* __restrict__ out) {
    gemm_body(yR, WoR, out, VD, D_DIM, blockIdx.x * 128, blockIdx.y * 128, 0);
}

// ---------------- fused per-token post: l2qk + dyn + betag + conv -------------------
// Writes packed scal[t*6+h] = {eg, beta, qk, -} for the scan.
__global__ __launch_bounds__(256)
void fused_post_kernel(const float* __restrict__ h,
                       const float* __restrict__ Wb, const float* __restrict__ Wa,
                       const float* __restrict__ A_log, const float* __restrict__ dt_bias,
                       float* __restrict__ q, float* __restrict__ k,
                       const float* __restrict__ dyn1, const float* __restrict__ w2,
                       const float* __restrict__ cw,
                       const float* __restrict__ x, float* __restrict__ v,
                       float* __restrict__ scal) {
    const int t = blockIdx.x;
    const int tid = threadIdx.x, wid = tid >> 5, lane = tid & 31;
    __shared__ float sdyn[4];
    __shared__ float red[8][12];

    if (wid < 6) {
        int vec = t * 6 + wid;
        float* qr = q + (size_t)vec * DKDIM;
        float* kr = k + (size_t)vec * DKDIM;
        float xq[8], xk[8];
        float sq = 0.f, sk = 0.f, sx = 0.f;
        #pragma unroll
        for (int i = 0; i < 8; i++) {
            xq[i] = qr[lane + 32*i]; xk[i] = kr[lane + 32*i];
            sq += xq[i]*xq[i]; sk += xk[i]*xk[i]; sx += xq[i]*xk[i];
        }
        #pragma unroll
        for (int off = 16; off; off >>= 1) {
            sq += __shfl_xor_sync(0xffffffffu, sq, off);
            sk += __shfl_xor_sync(0xffffffffu, sk, off);
            sx += __shfl_xor_sync(0xffffffffu, sx, off);
        }
        float rq = rsqrtf(sq + 1e-6f) * 0.0625f;   // fold DK^-0.5 into q
        float rk = rsqrtf(sk + 1e-6f);
        #pragma unroll
        for (int i = 0; i < 8; i++) {
            qr[lane + 32*i] = xq[i] * rq;
            kr[lane + 32*i] = xk[i] * rk;
        }
        if (lane == 0) scal[(size_t)vec * 4 + 2] = sx * rq * rk;   // qk
    } else if (wid == 6) {
        const float* r = dyn1 + (size_t)t * GENW;
        float a0 = 0.f, a1 = 0.f, a2 = 0.f, a3 = 0.f;
        #pragma unroll
        for (int i = 0; i < 8; i++) {
            int d = lane + 32*i;
            float vv = r[d];
            const float* w = w2 + d*4;
            a0 += vv*w[0]; a1 += vv*w[1]; a2 += vv*w[2]; a3 += vv*w[3];
        }
        #pragma unroll
        for (int off = 16; off; off >>= 1) {
            a0 += __shfl_xor_sync(0xffffffffu, a0, off);
            a1 += __shfl_xor_sync(0xffffffffu, a1, off);
            a2 += __shfl_xor_sync(0xffffffffu, a2, off);
            a3 += __shfl_xor_sync(0xffffffffu, a3, off);
        }
        if (lane == 0) { sdyn[0]=a0; sdyn[1]=a1; sdyn[2]=a2; sdyn[3]=a3; }
    }
    __syncthreads();

    const float* hr = h + (size_t)t * D_DIM;
    float acc[12];
    #pragma unroll
    for (int j = 0; j < 12; j++) acc[j] = 0.f;
    for (int d = tid; d < D_DIM; d += 256) {
        float hv = hr[d];
        const float* wb = Wb + d*6;
        const float* wa = Wa + d*6;
        #pragma unroll
        for (int j = 0; j < 6; j++) {
            acc[j]   += hv * wb[j];
            acc[6+j] += hv * wa[j];
        }
    }
    #pragma unroll
    for (int j = 0; j < 12; j++)
        #pragma unroll
        for (int off = 16; off; off >>= 1)
            acc[j] += __shfl_xor_sync(0xffffffffu, acc[j], off);
    if (lane == 0) {
        #pragma unroll
        for (int j = 0; j < 12; j++) red[wid][j] = acc[j];
    }
    __syncthreads();
    if (tid < 12) {
        float s = 0.f;
        #pragma unroll
        for (int i = 0; i < 8; i++) s += red[i][tid];
        if (tid < 6) {
            scal[(size_t)(t*6 + tid) * 4 + 1] = 1.0f / (1.0f + expf(-s));   // beta
        } else {
            int hh = tid - 6;
            float xx = s + dt_bias[hh];
            float sp = (xx > 20.0f) ? xx : log1pf(expf(xx));
            scal[(size_t)(t*6 + hh) * 4 + 0] = expf(-expf(A_log[hh]) * sp); // eg
        }
    }

    float dd[4];
    #pragma unroll
    for (int j = 0; j < 4; j++) dd[j] = sdyn[j];
    #pragma unroll
    for (int gi = 0; gi < 3; gi++) {
        int c = gi * 1024 + tid * 4;
        float a0 = 0.f, a1 = 0.f, a2 = 0.f, a3 = 0.f;
        #pragma unroll
        for (int j = 0; j < 4; j++) {
            int tt = t + j - 3;
            if (tt >= 0) {
                float4 xv = *(const float4*)(x + (size_t)tt * VD + c);
                a0 += (cw[(c+0)*4 + j] + dd[j]) * xv.x;
                a1 += (cw[(c+1)*4 + j] + dd[j]) * xv.y;
                a2 += (cw[(c+2)*4 + j] + dd[j]) * xv.z;
                a3 += (cw[(c+3)*4 + j] + dd[j]) * xv.w;
            }
        }
        float4 rr;
        rr.x = siluf(a0); rr.y = siluf(a1); rr.z = siluf(a2); rr.w = siluf(a3);
        *(float4*)(v + (size_t)t * VD + c) = rr;
    }
}

// ---------------- gated delta-rule scan: 1 column/warp, 3072 warps ----------------
// 768 blocks x 4 warps (~21 warps/SM = 5.2/SMSP): enough warps to hide the 5-level
// SHFL reduction chain. Lane owns 8 CONTIGUOUS DK values -> q/k are 2+2 LDG.128.
// Register double-buffered (2-step lookahead); no synchronization of any kind.
__global__ __launch_bounds__(128)
void scan_kernel(const float* __restrict__ q, const float* __restrict__ k,
                 const float* __restrict__ v, const float4* __restrict__ scal,
                 float* __restrict__ o) {
    const int warpg = blockIdx.x * 4 + (threadIdx.x >> 5);  // 0..3071 = column id
    const int c0    = warpg;                                // ONE column
    const int head  = c0 >> 9;
    const int lane  = threadIdx.x & 31;

    const float* qb = q + head * DKDIM + lane * 8;   // contiguous 8 floats per lane
    const float* kb = k + head * DKDIM + lane * 8;

    float s[8];
    #pragma unroll
    for (int i = 0; i < 8; i++) s[i] = 0.f;

    float4 qA0, qA1, kA0, kA1, scA; float vA;
    float4 qB0, qB1, kB0, kB1, scB; float vB;

    #define SCAN_LOAD(t, q0, q1, k0, k1, vv, sc) do {                  \
        size_t _off = (size_t)(t) * KD;                                \
        q0 = *(const float4*)(qb + _off);                              \
        q1 = *(const float4*)(qb + _off + 4);                          \
        k0 = *(const float4*)(kb + _off);                              \
        k1 = *(const float4*)(kb + _off + 4);                          \
        vv = v[(size_t)(t) * VD + c0];                                 \
        sc = scal[(t)*6 + head];                                       \
    } while (0)

    #define SCAN_STEP(t, q0, q1, k0, k1, vv, sc) do {                  \
        float eb = sc.x, bt = sc.y, qv = sc.z;                         \
        const float _qr[8] = {q0.x,q0.y,q0.z,q0.w,q1.x,q1.y,q1.z,q1.w};\
        const float _kr[8] = {k0.x,k0.y,k0.z,k0.w,k1.x,k1.y,k1.z,k1.w};\
        float d = 0.f, p = 0.f;                                        \
        _Pragma("unroll")                                              \
        for (int _i = 0; _i < 8; _i++) {                               \
            float t0 = s[_i] * eb;                                     \
            s[_i] = t0;                                                \
            d += _kr[_i] * t0;                                         \
            p += _qr[_i] * t0;                                         \
        }                                                              \
        _Pragma("unroll")                                              \
        for (int _off = 16; _off; _off >>= 1) {                        \
            d += __shfl_xor_sync(0xffffffffu, d, _off);                \
            p += __shfl_xor_sync(0xffffffffu, p, _off);                \
        }                                                              \
        float dv = (vv - d) * bt;                                      \
        _Pragma("unroll")                                              \
        for (int _i = 0; _i < 8; _i++) s[_i] += _kr[_i] * dv;          \
        if (lane == 0) o[(size_t)(t) * VD + c0] = p + qv * dv;         \
    } while (0)

    SCAN_LOAD(0, qA0, qA1, kA0, kA1, vA, scA);
    for (int t = 0; t < T_LEN; t += 2) {
        SCAN_LOAD(t + 1, qB0, qB1, kB0, kB1, vB, scB);
        SCAN_STEP(t, qA0, qA1, kA0, kA1, vA, scA);
        if (t + 2 < T_LEN) SCAN_LOAD(t + 2, qA0, qA1, kA0, kA1, vA, scA);
        SCAN_STEP(t + 1, qB0, qB1, kB0, kB1, vB, scB);
    }
    #undef SCAN_LOAD
    #undef SCAN_STEP
}

// ---------------- gated RMSNorm -> tf32-rounded, k-permuted y ----------------
__global__ __launch_bounds__(128)
void rmsnorm_gate_kernel(const float* __restrict__ o, const float* __restrict__ gate,
                         const float* __restrict__ nw, float* __restrict__ y) {
    int row = blockIdx.x;                  // t*6 + h
    int tid = threadIdx.x;
    size_t base = (size_t)(row / 6) * VD + (size_t)(row % 6) * DVDIM;
    int g = tid >> 2, a = tid & 3;

    float ov[4], gv[4], nv[4];
    float ss = 0.f;
    #pragma unroll
    for (int i = 0; i < 4; i++) {
        int c = g * 16 + a + 4 * i;
        ov[i] = o[base + c];
        gv[i] = gate[base + c];
        nv[i] = nw[c];
        ss += ov[i] * ov[i];
    }
    #pragma unroll
    for (int off = 16; off; off >>= 1) ss += __shfl_xor_sync(0xffffffffu, ss, off);
    __shared__ float red[4];
    int w = tid >> 5, lane = tid & 31;
    if (lane == 0) red[w] = ss;
    __syncthreads();
    float tot = red[0] + red[1] + red[2] + red[3];
    float rms = rsqrtf(tot * (1.0f / (float)DVDIM) + 1e-5f);

    float4 r;
    r.x = f2tf32f(ov[0] * rms * nv[0] * siluf(gv[0]));
    r.y = f2tf32f(ov[1] * rms * nv[1] * siluf(gv[1]));
    r.z = f2tf32f(ov[2] * rms * nv[2] * siluf(gv[2]));
    r.w = f2tf32f(ov[3] * rms * nv[3] * siluf(gv[3]));
    *(float4*)(y + base + g * 16 + 4 * a) = r;   // k-permuted slot
}

// ---------------- launch ----------------
extern "C" void kernel_launch(void* const* d_in, const int* in_sizes, int n_in,
                              void* d_out, int out_size) {
    const float* h       = (const float*)d_in[0];
    const float* Wq      = (const float*)d_in[1];
    const float* Wk      = (const float*)d_in[2];
    const float* Wv      = (const float*)d_in[3];
    const float* Wb      = (const float*)d_in[4];
    const float* Wa      = (const float*)d_in[5];
    const float* Wg      = (const float*)d_in[6];
    const float* Wo      = (const float*)d_in[7];
    const float* A_log   = (const float*)d_in[8];
    const float* dt_bias = (const float*)d_in[9];
    const float* conv_w  = (const float*)d_in[10];
    const float* gen_w1  = (const float*)d_in[11];
    const float* gen_w2  = (const float*)d_in[12];
    const float* norm_w  = (const float*)d_in[13];
    float* out = (float*)d_out;

    float *pq, *pk, *px, *pv, *pd1, *pgate, *po;
    float4* pscal;
    float *phr, *pwqr, *pwkr, *pwvr, *pwgr, *pg1r, *pwor;
    cudaGetSymbolAddress((void**)&pq,    g_q);
    cudaGetSymbolAddress((void**)&pk,    g_k);
    cudaGetSymbolAddress((void**)&px,    g_x);
    cudaGetSymbolAddress((void**)&pv,    g_v);
    cudaGetSymbolAddress((void**)&pd1,   g_dyn1);
    cudaGetSymbolAddress((void**)&pgate, g_gate);
    cudaGetSymbolAddress((void**)&po,    g_o);
    cudaGetSymbolAddress((void**)&pscal, g_scal);
    cudaGetSymbolAddress((void**)&phr,   g_hr);
    cudaGetSymbolAddress((void**)&pwqr,  g_wqr);
    cudaGetSymbolAddress((void**)&pwkr,  g_wkr);
    cudaGetSymbolAddress((void**)&pwvr,  g_wvr);
    cudaGetSymbolAddress((void**)&pwgr,  g_wgr);
    cudaGetSymbolAddress((void**)&pg1r,  g_g1r);
    cudaGetSymbolAddress((void**)&pwor,  g_wor);

    cudaFuncSetAttribute(proj_gemm_kernel, cudaFuncAttributeMaxDynamicSharedMemorySize, GEMM_SMEM);
    cudaFuncSetAttribute(wo_gemm_kernel,   cudaFuncAttributeMaxDynamicSharedMemorySize, GEMM_SMEM);

    // (0) round + permute h, transpose + round + permute weights
    prep_kernel<<<8320, 256>>>(h, Wq, Wk, Wv, Wg, gen_w1, Wo,
                               phr, pwqr, pwkr, pwvr, pwgr, pg1r, pwor);

    // (1) fused projections q|k|x|gate|dyn1 (74 x 32 tiles)
    proj_gemm_kernel<<<dim3(T_LEN/128, 74), 256, GEMM_SMEM>>>(
        phr, pwqr, pwkr, pwvr, pwgr, pg1r, pq, pk, px, pgate, pd1);

    // (2) fused per-token post-processing (writes packed scal)
    fused_post_kernel<<<T_LEN, 256>>>(h, Wb, Wa, A_log, dt_bias,
                                      pq, pk, pd1, gen_w2, conv_w,
                                      px, pv, (float*)pscal);

    // (3) scan: 1 column/warp, 3072 warps in 768 four-warp blocks
    scan_kernel<<<768, 128>>>(pq, pk, pv, pscal, po);

    // (4) gated RMSNorm -> permuted tf32 y (reuses g_x)
    rmsnorm_gate_kernel<<<T_LEN*H_N, 128>>>(po, pgate, norm_w, px);

    // (5) out = y @ Wo
    wo_gemm_kernel<<<dim3(T_LEN/128, D_DIM/128), 256, GEMM_SMEM>>>(px, pwor, out);
}

// round 13
// speedup vs baseline: 1.4838x; 1.1591x over previous
#include <cuda_runtime.h>
#include <cstdint>

// ---------------- problem constants ----------------
#define T_LEN 4096
#define D_DIM 2048
#define H_N   6
#define DKDIM 256
#define DVDIM 512
#define KD    1536   // H_N*DKDIM
#define VD    3072   // H_N*DVDIM
#define GENW  256
#define KSZ   4

// ---------------- scratch (static device, allocation-free) ----------------
__device__ float g_q[(size_t)T_LEN*KD];
__device__ float g_k[(size_t)T_LEN*KD];
__device__ float g_x[(size_t)T_LEN*VD];      // x = h@Wv; later reused as y (permuted tf32)
__device__ float g_v[(size_t)T_LEN*VD];      // conv+silu output
__device__ float g_dyn1[(size_t)T_LEN*GENW];
__device__ float g_gate[(size_t)T_LEN*VD];
__device__ float g_o[(size_t)T_LEN*VD];      // scan output
__device__ float4 g_scal[(size_t)T_LEN*H_N]; // packed {eg, beta, qk, -} per (t,head)

// tf32-rounded, k-permuted GEMM operands (weights also transposed to [N,K])
__device__ float g_hr [(size_t)T_LEN*D_DIM];
__device__ float g_wqr[(size_t)KD*D_DIM];
__device__ float g_wkr[(size_t)KD*D_DIM];
__device__ float g_wvr[(size_t)VD*D_DIM];
__device__ float g_wgr[(size_t)VD*D_DIM];
__device__ float g_g1r[(size_t)GENW*D_DIM];
__device__ float g_wor[(size_t)D_DIM*VD];

__device__ __forceinline__ float siluf(float x) { return x / (1.0f + expf(-x)); }

__device__ __forceinline__ float f2tf32f(float x) {
    uint32_t u;
    asm("cvt.rna.tf32.f32 %0, %1;" : "=r"(u) : "f"(x));
    return __uint_as_float(u);
}
__device__ __forceinline__ uint32_t smem_u32(const void* p) {
    uint32_t a;
    asm("{ .reg .u64 t; cvta.to.shared.u64 t, %1; cvt.u32.u64 %0, t; }" : "=r"(a) : "l"(p));
    return a;
}
__device__ __forceinline__ void cp16s(uint32_t sa, const void* g) {
    asm volatile("cp.async.cg.shared.global [%0], [%1], 16;" :: "r"(sa), "l"(g) : "memory");
}

// ---------------- prep: tf32 round + k-permute (+ weight transpose) ----------------
// Layout: within each 16-wide k group, element k stored at pos (k%4)*4 + k/4.
__global__ __launch_bounds__(256)
void prep_kernel(const float* __restrict__ h,
                 const float* __restrict__ wq, const float* __restrict__ wk,
                 const float* __restrict__ wv, const float* __restrict__ wg,
                 const float* __restrict__ g1, const float* __restrict__ wo,
                 float* __restrict__ hr,
                 float* __restrict__ wqr, float* __restrict__ wkr,
                 float* __restrict__ wvr, float* __restrict__ wgr,
                 float* __restrict__ g1r, float* __restrict__ wor) {
    int b = blockIdx.x;
    if (b < 2048) {          // h: round + permute, one 16-group per thread
        size_t e0 = ((size_t)b * 256 + threadIdx.x) * 16;
        float4 r0 = *(const float4*)(h + e0);
        float4 r1 = *(const float4*)(h + e0 + 4);
        float4 r2 = *(const float4*)(h + e0 + 8);
        float4 r3 = *(const float4*)(h + e0 + 12);
        float4 o0 = make_float4(f2tf32f(r0.x), f2tf32f(r1.x), f2tf32f(r2.x), f2tf32f(r3.x));
        float4 o1 = make_float4(f2tf32f(r0.y), f2tf32f(r1.y), f2tf32f(r2.y), f2tf32f(r3.y));
        float4 o2 = make_float4(f2tf32f(r0.z), f2tf32f(r1.z), f2tf32f(r2.z), f2tf32f(r3.z));
        float4 o3 = make_float4(f2tf32f(r0.w), f2tf32f(r1.w), f2tf32f(r2.w), f2tf32f(r3.w));
        *(float4*)(hr + e0)      = o0;
        *(float4*)(hr + e0 + 4)  = o1;
        *(float4*)(hr + e0 + 8)  = o2;
        *(float4*)(hr + e0 + 12) = o3;
        return;
    }
    b -= 2048;
    const float* W; float* O; int K, N;
    if (b < 768)                 { W = wq; O = wqr; K = D_DIM; N = KD; }
    else if ((b -= 768) < 768)   { W = wk; O = wkr; K = D_DIM; N = KD; }
    else if ((b -= 768) < 1536)  { W = wv; O = wvr; K = D_DIM; N = VD; }
    else if ((b -= 1536) < 1536) { W = wg; O = wgr; K = D_DIM; N = VD; }
    else if ((b -= 1536) < 128)  { W = g1; O = g1r; K = D_DIM; N = GENW; }
    else                         { b -= 128; W = wo; O = wor; K = VD; N = D_DIM; }
    int ntx = N >> 6;
    int tn = b % ntx, tk = b / ntx;
    int kb = tk * 64, nb = tn * 64;
    __shared__ float tile[64][65];
    int c = threadIdx.x & 63, r0i = threadIdx.x >> 6;
    #pragma unroll
    for (int i = 0; i < 16; i++) {
        int r = r0i + i * 4;
        tile[r][c] = W[(size_t)(kb + r) * N + nb + c];
    }
    __syncthreads();
    int nl = threadIdx.x >> 2, grp = threadIdx.x & 3;
    float* orow = O + (size_t)(nb + nl) * K + kb + grp * 16;
    #pragma unroll
    for (int a = 0; a < 4; a++) {
        float4 o;
        o.x = f2tf32f(tile[grp*16 + a     ][nl]);
        o.y = f2tf32f(tile[grp*16 + a + 4 ][nl]);
        o.z = f2tf32f(tile[grp*16 + a + 8 ][nl]);
        o.w = f2tf32f(tile[grp*16 + a + 12][nl]);
        *(float4*)(orow + a * 4) = o;
    }
}

// ---------------- tf32 GEMM body (permuted operands, LDS.128 frags) ----------------
// BK=16, 4-stage cp.async ring (64KB dyn smem), 256 threads, 2 CTAs/SM. (R6 config)
#define GEMM_SMEM 65536

__device__ __forceinline__ void gemm_body(
    const float* __restrict__ A, const float* __restrict__ B, float* __restrict__ C,
    int K, int Ns, int row0, int col0, int act)
{
    extern __shared__ float sm[];          // 4 stages x 4096 floats (A 2048 | B 2048)
    const int tid  = threadIdx.x;
    const int warp = tid >> 5, lane = tid & 31;
    const int gid  = lane >> 2, tig = lane & 3;
    const int wm   = warp >> 1, wn = warp & 1;
    const int KT   = K >> 4;
    const uint32_t smb = smem_u32(sm);

    float acc[2][8][4];
    #pragma unroll
    for (int i = 0; i < 2; i++)
        #pragma unroll
        for (int j = 0; j < 8; j++)
            #pragma unroll
            for (int cc = 0; cc < 4; cc++) acc[i][j][cc] = 0.0f;

    const int rA = tid >> 2,        cA = (tid & 3) * 4;
    const float* Abase = A + (size_t)(row0 + rA) * K + cA;
    const float* Bbase = B + (size_t)(col0 + rA) * K + cA;

    auto issue = [&](int kt) {
        if (kt < KT) {
            uint32_t so = smb + (uint32_t)(kt & 3) * 16384u + (uint32_t)(rA * 16 + cA) * 4u;
            int k0 = kt << 4;
            cp16s(so,                 Abase + k0);
            cp16s(so + 4096,          Abase + k0 + (size_t)64 * K);
            cp16s(so + 8192,          Bbase + k0);
            cp16s(so + 8192 + 4096,   Bbase + k0 + (size_t)64 * K);
        }
        asm volatile("cp.async.commit_group;" ::: "memory");
    };

    issue(0); issue(1); issue(2);
    for (int kt = 0; kt < KT; ++kt) {
        asm volatile("cp.async.wait_group 2;" ::: "memory");
        __syncthreads();
        issue(kt + 3);

        const float* As = sm + (kt & 3) * 4096;
        const float* Bs = As + 2048;

        float4 A0[2], A1[2];
        #pragma unroll
        for (int i = 0; i < 2; i++) {
            int m = wm * 32 + i * 16 + gid;
            A0[i] = *(const float4*)(As + m * 16 + tig * 4);
            A1[i] = *(const float4*)(As + (m + 8) * 16 + tig * 4);
        }
        #pragma unroll
        for (int jh = 0; jh < 2; jh++) {
            float4 Bv[4];
            #pragma unroll
            for (int j = 0; j < 4; j++) {
                int n = wn * 64 + (jh * 4 + j) * 8 + gid;
                Bv[j] = *(const float4*)(Bs + n * 16 + tig * 4);
            }
            #pragma unroll
            for (int i = 0; i < 2; i++)
                #pragma unroll
                for (int j = 0; j < 4; j++) {
                    float* ac = acc[i][jh * 4 + j];
                    asm volatile(
                        "mma.sync.aligned.m16n8k8.row.col.f32.tf32.tf32.f32 "
                        "{%0,%1,%2,%3}, {%4,%5,%6,%7}, {%8,%9}, {%0,%1,%2,%3};"
                        : "+f"(ac[0]), "+f"(ac[1]), "+f"(ac[2]), "+f"(ac[3])
                        : "r"(__float_as_uint(A0[i].x)), "r"(__float_as_uint(A1[i].x)),
                          "r"(__float_as_uint(A0[i].y)), "r"(__float_as_uint(A1[i].y)),
                          "r"(__float_as_uint(Bv[j].x)), "r"(__float_as_uint(Bv[j].y)));
                    asm volatile(
                        "mma.sync.aligned.m16n8k8.row.col.f32.tf32.tf32.f32 "
                        "{%0,%1,%2,%3}, {%4,%5,%6,%7}, {%8,%9}, {%0,%1,%2,%3};"
                        : "+f"(ac[0]), "+f"(ac[1]), "+f"(ac[2]), "+f"(ac[3])
                        : "r"(__float_as_uint(A0[i].z)), "r"(__float_as_uint(A1[i].z)),
                          "r"(__float_as_uint(A0[i].w)), "r"(__float_as_uint(A1[i].w)),
                          "r"(__float_as_uint(Bv[j].z)), "r"(__float_as_uint(Bv[j].w)));
                }
        }
    }

    #pragma unroll
    for (int i = 0; i < 2; ++i) {
        int row = row0 + wm * 32 + i * 16 + gid;
        #pragma unroll
        for (int j = 0; j < 8; ++j) {
            int col = col0 + wn * 64 + j * 8 + 2 * tig;
            float v0 = acc[i][j][0], v1 = acc[i][j][1];
            float v2 = acc[i][j][2], v3 = acc[i][j][3];
            if (act) { v0 = siluf(v0); v1 = siluf(v1); v2 = siluf(v2); v3 = siluf(v3); }
            *(float2*)(C + (size_t)row * Ns + col)       = make_float2(v0, v1);
            *(float2*)(C + (size_t)(row + 8) * Ns + col) = make_float2(v2, v3);
        }
    }
}

// fused projections q|k|x|gate|dyn1 (74 column tiles, single launch)
__global__ __launch_bounds__(256, 2)
void proj_gemm_kernel(const float* __restrict__ hR,
                      const float* __restrict__ WqR, const float* __restrict__ WkR,
                      const float* __restrict__ WvR, const float* __restrict__ WgR,
                      const float* __restrict__ g1R,
                      float* __restrict__ q, float* __restrict__ k,
                      float* __restrict__ x, float* __restrict__ g,
                      float* __restrict__ d1) {
    const int by = blockIdx.y;
    const float* B; float* C; int Ns, col0, act;
    if (by < 12)      { B = WqR; C = q;  Ns = KD;   col0 = by * 128;        act = 1; }
    else if (by < 24) { B = WkR; C = k;  Ns = KD;   col0 = (by - 12) * 128; act = 1; }
    else if (by < 48) { B = WvR; C = x;  Ns = VD;   col0 = (by - 24) * 128; act = 0; }
    else if (by < 72) { B = WgR; C = g;  Ns = VD;   col0 = (by - 48) * 128; act = 0; }
    else              { B = g1R; C = d1; Ns = GENW; col0 = (by - 72) * 128; act = 1; }
    gemm_body(hR, B, C, D_DIM, Ns, blockIdx.x * 128, col0, act);
}

__global__ __launch_bounds__(256, 2)
void wo_gemm_kernel(const float* __restrict__ yR, const float* __restrict__ WoR,
                    float* __restrict__ out) {
    gemm_body(yR, WoR, out, VD, D_DIM, blockIdx.x * 128, blockIdx.y * 128, 0);
}

// ---------------- fused per-token post: l2qk + dyn + betag + conv -------------------
// Writes packed scal[t*6+h] = {eg, beta, qk, -} for the scan.
__global__ __launch_bounds__(256)
void fused_post_kernel(const float* __restrict__ h,
                       const float* __restrict__ Wb, const float* __restrict__ Wa,
                       const float* __restrict__ A_log, const float* __restrict__ dt_bias,
                       float* __restrict__ q, float* __restrict__ k,
                       const float* __restrict__ dyn1, const float* __restrict__ w2,
                       const float* __restrict__ cw,
                       const float* __restrict__ x, float* __restrict__ v,
                       float* __restrict__ scal) {
    const int t = blockIdx.x;
    const int tid = threadIdx.x, wid = tid >> 5, lane = tid & 31;
    __shared__ float sdyn[4];
    __shared__ float red[8][12];

    if (wid < 6) {
        int vec = t * 6 + wid;
        float* qr = q + (size_t)vec * DKDIM;
        float* kr = k + (size_t)vec * DKDIM;
        float xq[8], xk[8];
        float sq = 0.f, sk = 0.f, sx = 0.f;
        #pragma unroll
        for (int i = 0; i < 8; i++) {
            xq[i] = qr[lane + 32*i]; xk[i] = kr[lane + 32*i];
            sq += xq[i]*xq[i]; sk += xk[i]*xk[i]; sx += xq[i]*xk[i];
        }
        #pragma unroll
        for (int off = 16; off; off >>= 1) {
            sq += __shfl_xor_sync(0xffffffffu, sq, off);
            sk += __shfl_xor_sync(0xffffffffu, sk, off);
            sx += __shfl_xor_sync(0xffffffffu, sx, off);
        }
        float rq = rsqrtf(sq + 1e-6f) * 0.0625f;   // fold DK^-0.5 into q
        float rk = rsqrtf(sk + 1e-6f);
        #pragma unroll
        for (int i = 0; i < 8; i++) {
            qr[lane + 32*i] = xq[i] * rq;
            kr[lane + 32*i] = xk[i] * rk;
        }
        if (lane == 0) scal[(size_t)vec * 4 + 2] = sx * rq * rk;   // qk
    } else if (wid == 6) {
        const float* r = dyn1 + (size_t)t * GENW;
        float a0 = 0.f, a1 = 0.f, a2 = 0.f, a3 = 0.f;
        #pragma unroll
        for (int i = 0; i < 8; i++) {
            int d = lane + 32*i;
            float vv = r[d];
            const float* w = w2 + d*4;
            a0 += vv*w[0]; a1 += vv*w[1]; a2 += vv*w[2]; a3 += vv*w[3];
        }
        #pragma unroll
        for (int off = 16; off; off >>= 1) {
            a0 += __shfl_xor_sync(0xffffffffu, a0, off);
            a1 += __shfl_xor_sync(0xffffffffu, a1, off);
            a2 += __shfl_xor_sync(0xffffffffu, a2, off);
            a3 += __shfl_xor_sync(0xffffffffu, a3, off);
        }
        if (lane == 0) { sdyn[0]=a0; sdyn[1]=a1; sdyn[2]=a2; sdyn[3]=a3; }
    }
    __syncthreads();

    const float* hr = h + (size_t)t * D_DIM;
    float acc[12];
    #pragma unroll
    for (int j = 0; j < 12; j++) acc[j] = 0.f;
    for (int d = tid; d < D_DIM; d += 256) {
        float hv = hr[d];
        const float* wb = Wb + d*6;
        const float* wa = Wa + d*6;
        #pragma unroll
        for (int j = 0; j < 6; j++) {
            acc[j]   += hv * wb[j];
            acc[6+j] += hv * wa[j];
        }
    }
    #pragma unroll
    for (int j = 0; j < 12; j++)
        #pragma unroll
        for (int off = 16; off; off >>= 1)
            acc[j] += __shfl_xor_sync(0xffffffffu, acc[j], off);
    if (lane == 0) {
        #pragma unroll
        for (int j = 0; j < 12; j++) red[wid][j] = acc[j];
    }
    __syncthreads();
    if (tid < 12) {
        float s = 0.f;
        #pragma unroll
        for (int i = 0; i < 8; i++) s += red[i][tid];
        if (tid < 6) {
            scal[(size_t)(t*6 + tid) * 4 + 1] = 1.0f / (1.0f + expf(-s));   // beta
        } else {
            int hh = tid - 6;
            float xx = s + dt_bias[hh];
            float sp = (xx > 20.0f) ? xx : log1pf(expf(xx));
            scal[(size_t)(t*6 + hh) * 4 + 0] = expf(-expf(A_log[hh]) * sp); // eg
        }
    }

    float dd[4];
    #pragma unroll
    for (int j = 0; j < 4; j++) dd[j] = sdyn[j];
    #pragma unroll
    for (int gi = 0; gi < 3; gi++) {
        int c = gi * 1024 + tid * 4;
        float a0 = 0.f, a1 = 0.f, a2 = 0.f, a3 = 0.f;
        #pragma unroll
        for (int j = 0; j < 4; j++) {
            int tt = t + j - 3;
            if (tt >= 0) {
                float4 xv = *(const float4*)(x + (size_t)tt * VD + c);
                a0 += (cw[(c+0)*4 + j] + dd[j]) * xv.x;
                a1 += (cw[(c+1)*4 + j] + dd[j]) * xv.y;
                a2 += (cw[(c+2)*4 + j] + dd[j]) * xv.z;
                a3 += (cw[(c+3)*4 + j] + dd[j]) * xv.w;
            }
        }
        float4 rr;
        rr.x = siluf(a0); rr.y = siluf(a1); rr.z = siluf(a2); rr.w = siluf(a3);
        *(float4*)(v + (size_t)t * VD + c) = rr;
    }
}

// ---------------- gated delta-rule scan: 2 cols/warp (R6 shape), vector loads ------
// 384 blocks x 4 warps = 1536 warps (the measured optimum). Lane owns 8 CONTIGUOUS
// DK floats -> q/k are 2+2 LDG.128; v one LDG.64; scalars one LDG.128 (packed).
// 21 -> 6 loads per warp-step at identical traffic. Register double-buffered,
// no synchronization, no register cap.
__global__ __launch_bounds__(128)
void scan_kernel(const float* __restrict__ q, const float* __restrict__ k,
                 const float* __restrict__ v, const float4* __restrict__ scal,
                 float* __restrict__ o) {
    const int warpg = blockIdx.x * 4 + (threadIdx.x >> 5);  // 0..1535
    const int c0    = warpg * 2;                            // two columns
    const int head  = c0 >> 9;
    const int lane  = threadIdx.x & 31;

    const float* qb = q + head * DKDIM + lane * 8;   // contiguous 8 floats per lane
    const float* kb = k + head * DKDIM + lane * 8;

    float s0[8], s1[8];
    #pragma unroll
    for (int i = 0; i < 8; i++) { s0[i] = 0.f; s1[i] = 0.f; }

    float4 qA0, qA1, kA0, kA1, scA; float2 vA;
    float4 qB0, qB1, kB0, kB1, scB; float2 vB;

    #define SCAN_LOAD(t, q0, q1, k0, k1, vv, sc) do {                  \
        size_t _off = (size_t)(t) * KD;                                \
        q0 = *(const float4*)(qb + _off);                              \
        q1 = *(const float4*)(qb + _off + 4);                          \
        k0 = *(const float4*)(kb + _off);                              \
        k1 = *(const float4*)(kb + _off + 4);                          \
        vv = *(const float2*)(v + (size_t)(t) * VD + c0);              \
        sc = scal[(t)*6 + head];                                       \
    } while (0)

    #define SCAN_STEP(t, q0, q1, k0, k1, vv, sc) do {                  \
        float eb = sc.x, bt = sc.y, qv = sc.z;                         \
        const float _qr[8] = {q0.x,q0.y,q0.z,q0.w,q1.x,q1.y,q1.z,q1.w};\
        const float _kr[8] = {k0.x,k0.y,k0.z,k0.w,k1.x,k1.y,k1.z,k1.w};\
        float d0 = 0.f, d1 = 0.f, p0 = 0.f, p1 = 0.f;                  \
        _Pragma("unroll")                                              \
        for (int _i = 0; _i < 8; _i++) {                               \
            float t0 = s0[_i] * eb, t1 = s1[_i] * eb;                  \
            s0[_i] = t0; s1[_i] = t1;                                  \
            d0 += _kr[_i] * t0; d1 += _kr[_i] * t1;                    \
            p0 += _qr[_i] * t0; p1 += _qr[_i] * t1;                    \
        }                                                              \
        _Pragma("unroll")                                              \
        for (int _off = 16; _off; _off >>= 1) {                        \
            d0 += __shfl_xor_sync(0xffffffffu, d0, _off);              \
            d1 += __shfl_xor_sync(0xffffffffu, d1, _off);              \
            p0 += __shfl_xor_sync(0xffffffffu, p0, _off);              \
            p1 += __shfl_xor_sync(0xffffffffu, p1, _off);              \
        }                                                              \
        float dv0 = (vv.x - d0) * bt, dv1 = (vv.y - d1) * bt;          \
        _Pragma("unroll")                                              \
        for (int _i = 0; _i < 8; _i++) {                               \
            s0[_i] += _kr[_i] * dv0; s1[_i] += _kr[_i] * dv1;          \
        }                                                              \
        if (lane == 0) {                                               \
            *(float2*)(o + (size_t)(t) * VD + c0) =                    \
                make_float2(p0 + qv * dv0, p1 + qv * dv1);             \
        }                                                              \
    } while (0)

    SCAN_LOAD(0, qA0, qA1, kA0, kA1, vA, scA);
    for (int t = 0; t < T_LEN; t += 2) {
        SCAN_LOAD(t + 1, qB0, qB1, kB0, kB1, vB, scB);
        SCAN_STEP(t, qA0, qA1, kA0, kA1, vA, scA);
        if (t + 2 < T_LEN) SCAN_LOAD(t + 2, qA0, qA1, kA0, kA1, vA, scA);
        SCAN_STEP(t + 1, qB0, qB1, kB0, kB1, vB, scB);
    }
    #undef SCAN_LOAD
    #undef SCAN_STEP
}

// ---------------- gated RMSNorm -> tf32-rounded, k-permuted y ----------------
__global__ __launch_bounds__(128)
void rmsnorm_gate_kernel(const float* __restrict__ o, const float* __restrict__ gate,
                         const float* __restrict__ nw, float* __restrict__ y) {
    int row = blockIdx.x;                  // t*6 + h
    int tid = threadIdx.x;
    size_t base = (size_t)(row / 6) * VD + (size_t)(row % 6) * DVDIM;
    int g = tid >> 2, a = tid & 3;

    float ov[4], gv[4], nv[4];
    float ss = 0.f;
    #pragma unroll
    for (int i = 0; i < 4; i++) {
        int c = g * 16 + a + 4 * i;
        ov[i] = o[base + c];
        gv[i] = gate[base + c];
        nv[i] = nw[c];
        ss += ov[i] * ov[i];
    }
    #pragma unroll
    for (int off = 16; off; off >>= 1) ss += __shfl_xor_sync(0xffffffffu, ss, off);
    __shared__ float red[4];
    int w = tid >> 5, lane = tid & 31;
    if (lane == 0) red[w] = ss;
    __syncthreads();
    float tot = red[0] + red[1] + red[2] + red[3];
    float rms = rsqrtf(tot * (1.0f / (float)DVDIM) + 1e-5f);

    float4 r;
    r.x = f2tf32f(ov[0] * rms * nv[0] * siluf(gv[0]));
    r.y = f2tf32f(ov[1] * rms * nv[1] * siluf(gv[1]));
    r.z = f2tf32f(ov[2] * rms * nv[2] * siluf(gv[2]));
    r.w = f2tf32f(ov[3] * rms * nv[3] * siluf(gv[3]));
    *(float4*)(y + base + g * 16 + 4 * a) = r;   // k-permuted slot
}

// ---------------- launch ----------------
extern "C" void kernel_launch(void* const* d_in, const int* in_sizes, int n_in,
                              void* d_out, int out_size) {
    const float* h       = (const float*)d_in[0];
    const float* Wq      = (const float*)d_in[1];
    const float* Wk      = (const float*)d_in[2];
    const float* Wv      = (const float*)d_in[3];
    const float* Wb      = (const float*)d_in[4];
    const float* Wa      = (const float*)d_in[5];
    const float* Wg      = (const float*)d_in[6];
    const float* Wo      = (const float*)d_in[7];
    const float* A_log   = (const float*)d_in[8];
    const float* dt_bias = (const float*)d_in[9];
    const float* conv_w  = (const float*)d_in[10];
    const float* gen_w1  = (const float*)d_in[11];
    const float* gen_w2  = (const float*)d_in[12];
    const float* norm_w  = (const float*)d_in[13];
    float* out = (float*)d_out;

    float *pq, *pk, *px, *pv, *pd1, *pgate, *po;
    float4* pscal;
    float *phr, *pwqr, *pwkr, *pwvr, *pwgr, *pg1r, *pwor;
    cudaGetSymbolAddress((void**)&pq,    g_q);
    cudaGetSymbolAddress((void**)&pk,    g_k);
    cudaGetSymbolAddress((void**)&px,    g_x);
    cudaGetSymbolAddress((void**)&pv,    g_v);
    cudaGetSymbolAddress((void**)&pd1,   g_dyn1);
    cudaGetSymbolAddress((void**)&pgate, g_gate);
    cudaGetSymbolAddress((void**)&po,    g_o);
    cudaGetSymbolAddress((void**)&pscal, g_scal);
    cudaGetSymbolAddress((void**)&phr,   g_hr);
    cudaGetSymbolAddress((void**)&pwqr,  g_wqr);
    cudaGetSymbolAddress((void**)&pwkr,  g_wkr);
    cudaGetSymbolAddress((void**)&pwvr,  g_wvr);
    cudaGetSymbolAddress((void**)&pwgr,  g_wgr);
    cudaGetSymbolAddress((void**)&pg1r,  g_g1r);
    cudaGetSymbolAddress((void**)&pwor,  g_wor);

    cudaFuncSetAttribute(proj_gemm_kernel, cudaFuncAttributeMaxDynamicSharedMemorySize, GEMM_SMEM);
    cudaFuncSetAttribute(wo_gemm_kernel,   cudaFuncAttributeMaxDynamicSharedMemorySize, GEMM_SMEM);

    // (0) round + permute h, transpose + round + permute weights
    prep_kernel<<<8320, 256>>>(h, Wq, Wk, Wv, Wg, gen_w1, Wo,
                               phr, pwqr, pwkr, pwvr, pwgr, pg1r, pwor);

    // (1) fused projections q|k|x|gate|dyn1 (74 x 32 tiles)
    proj_gemm_kernel<<<dim3(T_LEN/128, 74), 256, GEMM_SMEM>>>(
        phr, pwqr, pwkr, pwvr, pwgr, pg1r, pq, pk, px, pgate, pd1);

    // (2) fused per-token post-processing (writes packed scal)
    fused_post_kernel<<<T_LEN, 256>>>(h, Wb, Wa, A_log, dt_bias,
                                      pq, pk, pd1, gen_w2, conv_w,
                                      px, pv, (float*)pscal);

    // (3) scan: 2 cols/warp, 1536 warps, vectorized loads
    scan_kernel<<<384, 128>>>(pq, pk, pv, pscal, po);

    // (4) gated RMSNorm -> permuted tf32 y (reuses g_x)
    rmsnorm_gate_kernel<<<T_LEN*H_N, 128>>>(po, pgate, norm_w, px);

    // (5) out = y @ Wo
    wo_gemm_kernel<<<dim3(T_LEN/128, D_DIM/128), 256, GEMM_SMEM>>>(px, pwor, out);
}

// round 14
// speedup vs baseline: 1.8372x; 1.2381x over previous
#include <cuda_runtime.h>
#include <cstdint>

// ---------------- problem constants ----------------
#define T_LEN 4096
#define D_DIM 2048
#define H_N   6
#define DKDIM 256
#define DVDIM 512
#define KD    1536   // H_N*DKDIM
#define VD    3072   // H_N*DVDIM
#define GENW  256
#define KSZ   4

// ---------------- scratch (static device, allocation-free) ----------------
__device__ float g_q[(size_t)T_LEN*KD];
__device__ float g_k[(size_t)T_LEN*KD];
__device__ float g_x[(size_t)T_LEN*VD];      // x = h@Wv; later reused as y (permuted tf32)
__device__ float g_v[(size_t)T_LEN*VD];      // conv+silu output
__device__ float g_dyn1[(size_t)T_LEN*GENW];
__device__ float g_dyn[(size_t)T_LEN*4];
__device__ float g_gate[(size_t)T_LEN*VD];
__device__ float g_o[(size_t)T_LEN*VD];      // scan output
__device__ float4 g_scal[(size_t)T_LEN*H_N]; // {eg, beta, qk, kk|qx} per (t,head)

// tf32-rounded, k-permuted GEMM operands (weights also transposed to [N,K])
__device__ float g_hr [(size_t)T_LEN*D_DIM];
__device__ float g_wqr[(size_t)KD*D_DIM];
__device__ float g_wkr[(size_t)KD*D_DIM];
__device__ float g_wvr[(size_t)VD*D_DIM];
__device__ float g_wgr[(size_t)VD*D_DIM];
__device__ float g_g1r[(size_t)GENW*D_DIM];
__device__ float g_wor[(size_t)D_DIM*VD];

__device__ __forceinline__ float siluf(float x) { return x / (1.0f + expf(-x)); }

__device__ __forceinline__ float f2tf32f(float x) {
    uint32_t u;
    asm("cvt.rna.tf32.f32 %0, %1;" : "=r"(u) : "f"(x));
    return __uint_as_float(u);
}
__device__ __forceinline__ uint32_t smem_u32(const void* p) {
    uint32_t a;
    asm("{ .reg .u64 t; cvta.to.shared.u64 t, %1; cvt.u32.u64 %0, t; }" : "=r"(a) : "l"(p));
    return a;
}
__device__ __forceinline__ void cp16s(uint32_t sa, const void* g) {
    asm volatile("cp.async.cg.shared.global [%0], [%1], 16;" :: "r"(sa), "l"(g) : "memory");
}

// ---------------- prep: tf32 round + k-permute (+ weight transpose) ----------------
__global__ __launch_bounds__(256)
void prep_kernel(const float* __restrict__ h,
                 const float* __restrict__ wq, const float* __restrict__ wk,
                 const float* __restrict__ wv, const float* __restrict__ wg,
                 const float* __restrict__ g1, const float* __restrict__ wo,
                 float* __restrict__ hr,
                 float* __restrict__ wqr, float* __restrict__ wkr,
                 float* __restrict__ wvr, float* __restrict__ wgr,
                 float* __restrict__ g1r, float* __restrict__ wor) {
    int b = blockIdx.x;
    if (b < 2048) {
        size_t e0 = ((size_t)b * 256 + threadIdx.x) * 16;
        float4 r0 = *(const float4*)(h + e0);
        float4 r1 = *(const float4*)(h + e0 + 4);
        float4 r2 = *(const float4*)(h + e0 + 8);
        float4 r3 = *(const float4*)(h + e0 + 12);
        float4 o0 = make_float4(f2tf32f(r0.x), f2tf32f(r1.x), f2tf32f(r2.x), f2tf32f(r3.x));
        float4 o1 = make_float4(f2tf32f(r0.y), f2tf32f(r1.y), f2tf32f(r2.y), f2tf32f(r3.y));
        float4 o2 = make_float4(f2tf32f(r0.z), f2tf32f(r1.z), f2tf32f(r2.z), f2tf32f(r3.z));
        float4 o3 = make_float4(f2tf32f(r0.w), f2tf32f(r1.w), f2tf32f(r2.w), f2tf32f(r3.w));
        *(float4*)(hr + e0)      = o0;
        *(float4*)(hr + e0 + 4)  = o1;
        *(float4*)(hr + e0 + 8)  = o2;
        *(float4*)(hr + e0 + 12) = o3;
        return;
    }
    b -= 2048;
    const float* W; float* O; int K, N;
    if (b < 768)                 { W = wq; O = wqr; K = D_DIM; N = KD; }
    else if ((b -= 768) < 768)   { W = wk; O = wkr; K = D_DIM; N = KD; }
    else if ((b -= 768) < 1536)  { W = wv; O = wvr; K = D_DIM; N = VD; }
    else if ((b -= 1536) < 1536) { W = wg; O = wgr; K = D_DIM; N = VD; }
    else if ((b -= 1536) < 128)  { W = g1; O = g1r; K = D_DIM; N = GENW; }
    else                         { b -= 128; W = wo; O = wor; K = VD; N = D_DIM; }
    int ntx = N >> 6;
    int tn = b % ntx, tk = b / ntx;
    int kb = tk * 64, nb = tn * 64;
    __shared__ float tile[64][65];
    int c = threadIdx.x & 63, r0i = threadIdx.x >> 6;
    #pragma unroll
    for (int i = 0; i < 16; i++) {
        int r = r0i + i * 4;
        tile[r][c] = W[(size_t)(kb + r) * N + nb + c];
    }
    __syncthreads();
    int nl = threadIdx.x >> 2, grp = threadIdx.x & 3;
    float* orow = O + (size_t)(nb + nl) * K + kb + grp * 16;
    #pragma unroll
    for (int a = 0; a < 4; a++) {
        float4 o;
        o.x = f2tf32f(tile[grp*16 + a     ][nl]);
        o.y = f2tf32f(tile[grp*16 + a + 4 ][nl]);
        o.z = f2tf32f(tile[grp*16 + a + 8 ][nl]);
        o.w = f2tf32f(tile[grp*16 + a + 12][nl]);
        *(float4*)(orow + a * 4) = o;
    }
}

// ---------------- tf32 GEMM body (permuted operands, LDS.128 frags) ----------------
#define GEMM_SMEM 65536

__device__ __forceinline__ void gemm_body(
    const float* __restrict__ A, const float* __restrict__ B, float* __restrict__ C,
    int K, int Ns, int row0, int col0, int act)
{
    extern __shared__ float sm[];
    const int tid  = threadIdx.x;
    const int warp = tid >> 5, lane = tid & 31;
    const int gid  = lane >> 2, tig = lane & 3;
    const int wm   = warp >> 1, wn = warp & 1;
    const int KT   = K >> 4;
    const uint32_t smb = smem_u32(sm);

    float acc[2][8][4];
    #pragma unroll
    for (int i = 0; i < 2; i++)
        #pragma unroll
        for (int j = 0; j < 8; j++)
            #pragma unroll
            for (int cc = 0; cc < 4; cc++) acc[i][j][cc] = 0.0f;

    const int rA = tid >> 2,        cA = (tid & 3) * 4;
    const float* Abase = A + (size_t)(row0 + rA) * K + cA;
    const float* Bbase = B + (size_t)(col0 + rA) * K + cA;

    auto issue = [&](int kt) {
        if (kt < KT) {
            uint32_t so = smb + (uint32_t)(kt & 3) * 16384u + (uint32_t)(rA * 16 + cA) * 4u;
            int k0 = kt << 4;
            cp16s(so,                 Abase + k0);
            cp16s(so + 4096,          Abase + k0 + (size_t)64 * K);
            cp16s(so + 8192,          Bbase + k0);
            cp16s(so + 8192 + 4096,   Bbase + k0 + (size_t)64 * K);
        }
        asm volatile("cp.async.commit_group;" ::: "memory");
    };

    issue(0); issue(1); issue(2);
    for (int kt = 0; kt < KT; ++kt) {
        asm volatile("cp.async.wait_group 2;" ::: "memory");
        __syncthreads();
        issue(kt + 3);

        const float* As = sm + (kt & 3) * 4096;
        const float* Bs = As + 2048;

        float4 A0[2], A1[2];
        #pragma unroll
        for (int i = 0; i < 2; i++) {
            int m = wm * 32 + i * 16 + gid;
            A0[i] = *(const float4*)(As + m * 16 + tig * 4);
            A1[i] = *(const float4*)(As + (m + 8) * 16 + tig * 4);
        }
        #pragma unroll
        for (int jh = 0; jh < 2; jh++) {
            float4 Bv[4];
            #pragma unroll
            for (int j = 0; j < 4; j++) {
                int n = wn * 64 + (jh * 4 + j) * 8 + gid;
                Bv[j] = *(const float4*)(Bs + n * 16 + tig * 4);
            }
            #pragma unroll
            for (int i = 0; i < 2; i++)
                #pragma unroll
                for (int j = 0; j < 4; j++) {
                    float* ac = acc[i][jh * 4 + j];
                    asm volatile(
                        "mma.sync.aligned.m16n8k8.row.col.f32.tf32.tf32.f32 "
                        "{%0,%1,%2,%3}, {%4,%5,%6,%7}, {%8,%9}, {%0,%1,%2,%3};"
                        : "+f"(ac[0]), "+f"(ac[1]), "+f"(ac[2]), "+f"(ac[3])
                        : "r"(__float_as_uint(A0[i].x)), "r"(__float_as_uint(A1[i].x)),
                          "r"(__float_as_uint(A0[i].y)), "r"(__float_as_uint(A1[i].y)),
                          "r"(__float_as_uint(Bv[j].x)), "r"(__float_as_uint(Bv[j].y)));
                    asm volatile(
                        "mma.sync.aligned.m16n8k8.row.col.f32.tf32.tf32.f32 "
                        "{%0,%1,%2,%3}, {%4,%5,%6,%7}, {%8,%9}, {%0,%1,%2,%3};"
                        : "+f"(ac[0]), "+f"(ac[1]), "+f"(ac[2]), "+f"(ac[3])
                        : "r"(__float_as_uint(A0[i].z)), "r"(__float_as_uint(A1[i].z)),
                          "r"(__float_as_uint(A0[i].w)), "r"(__float_as_uint(A1[i].w)),
                          "r"(__float_as_uint(Bv[j].z)), "r"(__float_as_uint(Bv[j].w)));
                }
        }
    }

    #pragma unroll
    for (int i = 0; i < 2; ++i) {
        int row = row0 + wm * 32 + i * 16 + gid;
        #pragma unroll
        for (int j = 0; j < 8; ++j) {
            int col = col0 + wn * 64 + j * 8 + 2 * tig;
            float v0 = acc[i][j][0], v1 = acc[i][j][1];
            float v2 = acc[i][j][2], v3 = acc[i][j][3];
            if (act) { v0 = siluf(v0); v1 = siluf(v1); v2 = siluf(v2); v3 = siluf(v3); }
            *(float2*)(C + (size_t)row * Ns + col)       = make_float2(v0, v1);
            *(float2*)(C + (size_t)(row + 8) * Ns + col) = make_float2(v2, v3);
        }
    }
}

__global__ __launch_bounds__(256, 2)
void proj_gemm_kernel(const float* __restrict__ hR,
                      const float* __restrict__ WqR, const float* __restrict__ WkR,
                      const float* __restrict__ WvR, const float* __restrict__ WgR,
                      const float* __restrict__ g1R,
                      float* __restrict__ q, float* __restrict__ k,
                      float* __restrict__ x, float* __restrict__ g,
                      float* __restrict__ d1) {
    const int by = blockIdx.y;
    const float* B; float* C; int Ns, col0, act;
    if (by < 12)      { B = WqR; C = q;  Ns = KD;   col0 = by * 128;        act = 1; }
    else if (by < 24) { B = WkR; C = k;  Ns = KD;   col0 = (by - 12) * 128; act = 1; }
    else if (by < 48) { B = WvR; C = x;  Ns = VD;   col0 = (by - 24) * 128; act = 0; }
    else if (by < 72) { B = WgR; C = g;  Ns = VD;   col0 = (by - 48) * 128; act = 0; }
    else              { B = g1R; C = d1; Ns = GENW; col0 = (by - 72) * 128; act = 1; }
    gemm_body(hR, B, C, D_DIM, Ns, blockIdx.x * 128, col0, act);
}

__global__ __launch_bounds__(256, 2)
void wo_gemm_kernel(const float* __restrict__ yR, const float* __restrict__ WoR,
                    float* __restrict__ out) {
    gemm_body(yR, WoR, out, VD, D_DIM, blockIdx.x * 128, blockIdx.y * 128, 0);
}

// ---------------- dyn = dyn1[T,256] @ gen_w2[256,4] (warp per token) ----------------
__global__ __launch_bounds__(256)
void dyn2_kernel(const float* __restrict__ dyn1, const float* __restrict__ w2,
                 float* __restrict__ dyn) {
    int t    = blockIdx.x * 8 + (threadIdx.x >> 5);
    int lane = threadIdx.x & 31;
    const float* r = dyn1 + (size_t)t * GENW;
    float a0 = 0.f, a1 = 0.f, a2 = 0.f, a3 = 0.f;
    #pragma unroll
    for (int i = 0; i < 8; i++) {
        int d = lane + 32*i;
        float v = r[d];
        const float* w = w2 + d*4;
        a0 += v*w[0]; a1 += v*w[1]; a2 += v*w[2]; a3 += v*w[3];
    }
    #pragma unroll
    for (int off = 16; off; off >>= 1) {
        a0 += __shfl_xor_sync(0xffffffffu, a0, off);
        a1 += __shfl_xor_sync(0xffffffffu, a1, off);
        a2 += __shfl_xor_sync(0xffffffffu, a2, off);
        a3 += __shfl_xor_sync(0xffffffffu, a3, off);
    }
    if (lane == 0) {
        dyn[t*4+0] = a0; dyn[t*4+1] = a1; dyn[t*4+2] = a2; dyn[t*4+3] = a3;
    }
}

// ---------------- betag -> scal.{x,y} ----------------
__global__ __launch_bounds__(256)
void betag_kernel(const float* __restrict__ h, const float* __restrict__ Wb,
                  const float* __restrict__ Wa, const float* __restrict__ A_log,
                  const float* __restrict__ dt_bias, float* __restrict__ scal) {
    int t = blockIdx.x;
    const float* hr = h + (size_t)t * D_DIM;
    float acc[12];
    #pragma unroll
    for (int j = 0; j < 12; j++) acc[j] = 0.f;
    for (int d = threadIdx.x; d < D_DIM; d += 256) {
        float hv = hr[d];
        const float* wb = Wb + d*6;
        const float* wa = Wa + d*6;
        #pragma unroll
        for (int j = 0; j < 6; j++) {
            acc[j]   += hv * wb[j];
            acc[6+j] += hv * wa[j];
        }
    }
    #pragma unroll
    for (int j = 0; j < 12; j++)
        #pragma unroll
        for (int off = 16; off; off >>= 1)
            acc[j] += __shfl_xor_sync(0xffffffffu, acc[j], off);

    __shared__ float red[8][12];
    int w = threadIdx.x >> 5, lane = threadIdx.x & 31;
    if (lane == 0) {
        #pragma unroll
        for (int j = 0; j < 12; j++) red[w][j] = acc[j];
    }
    __syncthreads();
    if (threadIdx.x < 12) {
        float s = 0.f;
        #pragma unroll
        for (int i = 0; i < 8; i++) s += red[i][threadIdx.x];
        int j = threadIdx.x;
        if (j < 6) {
            scal[(size_t)(t*6 + j) * 4 + 1] = 1.0f / (1.0f + expf(-s));     // beta
        } else {
            int hh = j - 6;
            float xx = s + dt_bias[hh];
            float sp = (xx > 20.0f) ? xx : log1pf(expf(xx));
            scal[(size_t)(t*6 + hh) * 4 + 0] = expf(-expf(A_log[hh]) * sp); // eg
        }
    }
}

// ---------------- dynamic short conv + silu ----------------
__global__ __launch_bounds__(256)
void conv_silu_kernel(const float* __restrict__ x, const float* __restrict__ dyn,
                      const float* __restrict__ cw, float* __restrict__ v) {
    int idx = blockIdx.x * 256 + threadIdx.x;
    int t = idx / (VD/4);
    if (t >= T_LEN) return;
    int c = (idx - t * (VD/4)) * 4;
    float d[4];
    #pragma unroll
    for (int j = 0; j < 4; j++) d[j] = dyn[t*4 + j];
    float a0 = 0.f, a1 = 0.f, a2 = 0.f, a3 = 0.f;
    #pragma unroll
    for (int j = 0; j < 4; j++) {
        int tt = t + j - 3;
        if (tt >= 0) {
            float4 xv = *(const float4*)(x + (size_t)tt * VD + c);
            a0 += (cw[(c+0)*4 + j] + d[j]) * xv.x;
            a1 += (cw[(c+1)*4 + j] + d[j]) * xv.y;
            a2 += (cw[(c+2)*4 + j] + d[j]) * xv.z;
            a3 += (cw[(c+3)*4 + j] + d[j]) * xv.w;
        }
    }
    float4 r;
    r.x = siluf(a0); r.y = siluf(a1); r.z = siluf(a2); r.w = siluf(a3);
    *(float4*)(v + (size_t)t * VD + c) = r;
}

// ---------------- l2norm(q,k) + qk -> scal.z (warp per (t,h)) ----------------
__global__ __launch_bounds__(256)
void l2qk_kernel(float* __restrict__ q, float* __restrict__ k, float* __restrict__ scal) {
    int vec  = blockIdx.x * 8 + (threadIdx.x >> 5);   // t*6 + h
    int lane = threadIdx.x & 31;
    float* qr = q + (size_t)vec * DKDIM;
    float* kr = k + (size_t)vec * DKDIM;
    float xq[8], xk[8];
    float sq = 0.f, sk = 0.f, sx = 0.f;
    #pragma unroll
    for (int i = 0; i < 8; i++) {
        xq[i] = qr[lane + 32*i]; xk[i] = kr[lane + 32*i];
        sq += xq[i]*xq[i]; sk += xk[i]*xk[i]; sx += xq[i]*xk[i];
    }
    #pragma unroll
    for (int off = 16; off; off >>= 1) {
        sq += __shfl_xor_sync(0xffffffffu, sq, off);
        sk += __shfl_xor_sync(0xffffffffu, sk, off);
        sx += __shfl_xor_sync(0xffffffffu, sx, off);
    }
    float rq = rsqrtf(sq + 1e-6f) * 0.0625f;   // fold DK^-0.5 into q
    float rk = rsqrtf(sk + 1e-6f);
    #pragma unroll
    for (int i = 0; i < 8; i++) {
        qr[lane + 32*i] = xq[i] * rq;
        kr[lane + 32*i] = xk[i] * rk;
    }
    if (lane == 0) scal[(size_t)vec * 4 + 2] = sx * rq * rk;
}

// ---------------- cross products for the paired scan -> scal.w ----------------
// For even t: scal[t*6+h].w   = kk = k_{t+1}·k_t       (post-norm)
//             scal[(t+1)*6+h].w = qx = q_{t+1}·k_t     (post-norm, q scaled)
__global__ __launch_bounds__(256)
void cross_kernel(const float* __restrict__ q, const float* __restrict__ k,
                  float* __restrict__ scal) {
    int wg   = blockIdx.x * 8 + (threadIdx.x >> 5);   // 0..12287 = pair*6 + head
    int lane = threadIdx.x & 31;
    int pair = wg / 6, head = wg - pair * 6;
    int t = pair * 2;
    const float* k0 = k + ((size_t)t * 6 + head) * DKDIM;
    const float* k1 = k + ((size_t)(t + 1) * 6 + head) * DKDIM;
    const float* q1 = q + ((size_t)(t + 1) * 6 + head) * DKDIM;
    float kk = 0.f, qx = 0.f;
    #pragma unroll
    for (int i = 0; i < 8; i++) {
        int d = lane + 32 * i;
        float kv = k0[d];
        kk += k1[d] * kv;
        qx += q1[d] * kv;
    }
    #pragma unroll
    for (int off = 16; off; off >>= 1) {
        kk += __shfl_xor_sync(0xffffffffu, kk, off);
        qx += __shfl_xor_sync(0xffffffffu, qx, off);
    }
    if (lane == 0) {
        scal[((size_t)t * 6 + head) * 4 + 3]       = kk;
        scal[((size_t)(t + 1) * 6 + head) * 4 + 3] = qx;
    }
}

// ---------------- paired gated delta-rule scan: 2 cols/warp, 2 steps fused --------
// 384 blocks x 4 warps (R6 optimum). Scalar stride-32 loads (proven optimal).
// One 5-level butterfly (8 values) per PAIR of steps instead of per step.
__global__ __launch_bounds__(128)
void scan_kernel(const float* __restrict__ q, const float* __restrict__ k,
                 const float* __restrict__ v, const float4* __restrict__ scal,
                 float* __restrict__ o) {
    const int warpg = blockIdx.x * 4 + (threadIdx.x >> 5);
    const int c0    = warpg * 2;
    const int head  = c0 >> 9;
    const int lane  = threadIdx.x & 31;

    const float* qb = q + head * DKDIM + lane;
    const float* kb = k + head * DKDIM + lane;

    float s0[8], s1[8];
    #pragma unroll
    for (int i = 0; i < 8; i++) { s0[i] = 0.f; s1[i] = 0.f; }

    // pair buffers A/B: q,k for both tokens + v + scal
    float qa0[8], ka0[8], qa1[8], ka1[8]; float2 va0, va1; float4 sa0, sa1;
    float qb0[8], kb0[8], qb1[8], kb1[8]; float2 vb0, vb1; float4 sb0, sb1;

    #define PAIR_LOAD(t, Q0, K0, Q1, K1, V0, V1, S0_, S1_) do {        \
        size_t _o0 = (size_t)(t) * KD, _o1 = (size_t)((t)+1) * KD;     \
        _Pragma("unroll")                                              \
        for (int _i = 0; _i < 8; _i++) {                               \
            Q0[_i] = qb[_o0 + 32*_i];  K0[_i] = kb[_o0 + 32*_i];       \
            Q1[_i] = qb[_o1 + 32*_i];  K1[_i] = kb[_o1 + 32*_i];       \
        }                                                              \
        V0 = *(const float2*)(v + (size_t)(t) * VD + c0);              \
        V1 = *(const float2*)(v + (size_t)((t)+1) * VD + c0);          \
        S0_ = scal[(t)*6 + head];                                      \
        S1_ = scal[((t)+1)*6 + head];                                  \
    } while (0)

    #define PAIR_STEP(t, Q0, K0, Q1, K1, V0, V1, S0_, S1_) do {        \
        float E1 = S0_.x, b0c = S0_.y, qk0 = S0_.z, kkc = S0_.w;       \
        float E2 = S1_.x, b1c = S1_.y, qk1 = S1_.z, qxc = S1_.w;       \
        float E12 = E1 * E2;                                           \
        /* 4 reductions x 2 columns over pre-pair state */             \
        float rA0=0.f,rB0=0.f,rC0=0.f,rD0=0.f;                         \
        float rA1=0.f,rB1=0.f,rC1=0.f,rD1=0.f;                         \
        _Pragma("unroll")                                              \
        for (int _i = 0; _i < 8; _i++) {                               \
            float t0 = s0[_i], t1 = s1[_i];                            \
            rA0 += K0[_i]*t0; rA1 += K0[_i]*t1;                        \
            rB0 += Q0[_i]*t0; rB1 += Q0[_i]*t1;                        \
            rC0 += K1[_i]*t0; rC1 += K1[_i]*t1;                        \
            rD0 += Q1[_i]*t0; rD1 += Q1[_i]*t1;                        \
        }                                                              \
        _Pragma("unroll")                                              \
        for (int _off = 16; _off; _off >>= 1) {                        \
            rA0 += __shfl_xor_sync(0xffffffffu, rA0, _off);            \
            rA1 += __shfl_xor_sync(0xffffffffu, rA1, _off);            \
            rB0 += __shfl_xor_sync(0xffffffffu, rB0, _off);            \
            rB1 += __shfl_xor_sync(0xffffffffu, rB1, _off);            \
            rC0 += __shfl_xor_sync(0xffffffffu, rC0, _off);            \
            rC1 += __shfl_xor_sync(0xffffffffu, rC1, _off);            \
            rD0 += __shfl_xor_sync(0xffffffffu, rD0, _off);            \
            rD1 += __shfl_xor_sync(0xffffffffu, rD1, _off);            \
        }                                                              \
        /* column 0 scalars */                                         \
        float dv0_0 = (V0.x - E1*rA0) * b0c;                           \
        float d1_0  = E12*rC0 + E2*kkc*dv0_0;                          \
        float dv1_0 = (V1.x - d1_0) * b1c;                             \
        /* column 1 scalars */                                         \
        float dv0_1 = (V0.y - E1*rA1) * b0c;                           \
        float d1_1  = E12*rC1 + E2*kkc*dv0_1;                          \
        float dv1_1 = (V1.y - d1_1) * b1c;                             \
        if (lane == 0) {                                               \
            *(float2*)(o + (size_t)(t) * VD + c0) = make_float2(       \
                E1*rB0 + qk0*dv0_0, E1*rB1 + qk0*dv0_1);               \
            *(float2*)(o + (size_t)((t)+1) * VD + c0) = make_float2(   \
                E12*rD0 + E2*qxc*dv0_0 + qk1*dv1_0,                    \
                E12*rD1 + E2*qxc*dv0_1 + qk1*dv1_1);                   \
        }                                                              \
        /* state update: s = E12*s + (E2*dv0)*k0 + dv1*k1 */           \
        float e2d0 = E2 * dv0_0, e2d1 = E2 * dv0_1;                    \
        _Pragma("unroll")                                              \
        for (int _i = 0; _i < 8; _i++) {                               \
            s0[_i] = E12*s0[_i] + e2d0*K0[_i] + dv1_0*K1[_i];          \
            s1[_i] = E12*s1[_i] + e2d1*K0[_i] + dv1_1*K1[_i];          \
        }                                                              \
    } while (0)

    PAIR_LOAD(0, qa0, ka0, qa1, ka1, va0, va1, sa0, sa1);
    for (int t = 0; t < T_LEN; t += 4) {
        PAIR_LOAD(t + 2, qb0, kb0, qb1, kb1, vb0, vb1, sb0, sb1);
        PAIR_STEP(t, qa0, ka0, qa1, ka1, va0, va1, sa0, sa1);
        if (t + 4 < T_LEN) PAIR_LOAD(t + 4, qa0, ka0, qa1, ka1, va0, va1, sa0, sa1);
        PAIR_STEP(t + 2, qb0, kb0, qb1, kb1, vb0, vb1, sb0, sb1);
    }
    #undef PAIR_LOAD
    #undef PAIR_STEP
}

// ---------------- gated RMSNorm -> tf32-rounded, k-permuted y ----------------
__global__ __launch_bounds__(128)
void rmsnorm_gate_kernel(const float* __restrict__ o, const float* __restrict__ gate,
                         const float* __restrict__ nw, float* __restrict__ y) {
    int row = blockIdx.x;                  // t*6 + h
    int tid = threadIdx.x;
    size_t base = (size_t)(row / 6) * VD + (size_t)(row % 6) * DVDIM;
    int g = tid >> 2, a = tid & 3;

    float ov[4], gv[4], nv[4];
    float ss = 0.f;
    #pragma unroll
    for (int i = 0; i < 4; i++) {
        int c = g * 16 + a + 4 * i;
        ov[i] = o[base + c];
        gv[i] = gate[base + c];
        nv[i] = nw[c];
        ss += ov[i] * ov[i];
    }
    #pragma unroll
    for (int off = 16; off; off >>= 1) ss += __shfl_xor_sync(0xffffffffu, ss, off);
    __shared__ float red[4];
    int w = tid >> 5, lane = tid & 31;
    if (lane == 0) red[w] = ss;
    __syncthreads();
    float tot = red[0] + red[1] + red[2] + red[3];
    float rms = rsqrtf(tot * (1.0f / (float)DVDIM) + 1e-5f);

    float4 r;
    r.x = f2tf32f(ov[0] * rms * nv[0] * siluf(gv[0]));
    r.y = f2tf32f(ov[1] * rms * nv[1] * siluf(gv[1]));
    r.z = f2tf32f(ov[2] * rms * nv[2] * siluf(gv[2]));
    r.w = f2tf32f(ov[3] * rms * nv[3] * siluf(gv[3]));
    *(float4*)(y + base + g * 16 + 4 * a) = r;
}

// ---------------- launch ----------------
extern "C" void kernel_launch(void* const* d_in, const int* in_sizes, int n_in,
                              void* d_out, int out_size) {
    const float* h       = (const float*)d_in[0];
    const float* Wq      = (const float*)d_in[1];
    const float* Wk      = (const float*)d_in[2];
    const float* Wv      = (const float*)d_in[3];
    const float* Wb      = (const float*)d_in[4];
    const float* Wa      = (const float*)d_in[5];
    const float* Wg      = (const float*)d_in[6];
    const float* Wo      = (const float*)d_in[7];
    const float* A_log   = (const float*)d_in[8];
    const float* dt_bias = (const float*)d_in[9];
    const float* conv_w  = (const float*)d_in[10];
    const float* gen_w1  = (const float*)d_in[11];
    const float* gen_w2  = (const float*)d_in[12];
    const float* norm_w  = (const float*)d_in[13];
    float* out = (float*)d_out;

    float *pq, *pk, *px, *pv, *pd1, *pd, *pgate, *po;
    float4* pscal;
    float *phr, *pwqr, *pwkr, *pwvr, *pwgr, *pg1r, *pwor;
    cudaGetSymbolAddress((void**)&pq,    g_q);
    cudaGetSymbolAddress((void**)&pk,    g_k);
    cudaGetSymbolAddress((void**)&px,    g_x);
    cudaGetSymbolAddress((void**)&pv,    g_v);
    cudaGetSymbolAddress((void**)&pd1,   g_dyn1);
    cudaGetSymbolAddress((void**)&pd,    g_dyn);
    cudaGetSymbolAddress((void**)&pgate, g_gate);
    cudaGetSymbolAddress((void**)&po,    g_o);
    cudaGetSymbolAddress((void**)&pscal, g_scal);
    cudaGetSymbolAddress((void**)&phr,   g_hr);
    cudaGetSymbolAddress((void**)&pwqr,  g_wqr);
    cudaGetSymbolAddress((void**)&pwkr,  g_wkr);
    cudaGetSymbolAddress((void**)&pwvr,  g_wvr);
    cudaGetSymbolAddress((void**)&pwgr,  g_wgr);
    cudaGetSymbolAddress((void**)&pg1r,  g_g1r);
    cudaGetSymbolAddress((void**)&pwor,  g_wor);

    cudaFuncSetAttribute(proj_gemm_kernel, cudaFuncAttributeMaxDynamicSharedMemorySize, GEMM_SMEM);
    cudaFuncSetAttribute(wo_gemm_kernel,   cudaFuncAttributeMaxDynamicSharedMemorySize, GEMM_SMEM);

    // (0) round + permute h, transpose + round + permute weights
    prep_kernel<<<8320, 256>>>(h, Wq, Wk, Wv, Wg, gen_w1, Wo,
                               phr, pwqr, pwkr, pwvr, pwgr, pg1r, pwor);

    // (1) fused projections q|k|x|gate|dyn1 (74 x 32 tiles)
    proj_gemm_kernel<<<dim3(T_LEN/128, 74), 256, GEMM_SMEM>>>(
        phr, pwqr, pwkr, pwvr, pwgr, pg1r, pq, pk, px, pgate, pd1);

    // (2..5) elementwise stages (R6 shapes)
    dyn2_kernel<<<T_LEN/8, 256>>>(pd1, gen_w2, pd);
    betag_kernel<<<T_LEN, 256>>>(h, Wb, Wa, A_log, dt_bias, (float*)pscal);
    conv_silu_kernel<<<(T_LEN*(VD/4))/256, 256>>>(px, pd, conv_w, pv);
    l2qk_kernel<<<(T_LEN*H_N)/8, 256>>>(pq, pk, (float*)pscal);
    cross_kernel<<<(T_LEN/2*H_N)/8, 256>>>(pq, pk, (float*)pscal);

    // (6) paired two-step scan
    scan_kernel<<<384, 128>>>(pq, pk, pv, pscal, po);

    // (7) gated RMSNorm -> permuted tf32 y (reuses g_x)
    rmsnorm_gate_kernel<<<T_LEN*H_N, 128>>>(po, pgate, norm_w, px);

    // (8) out = y @ Wo
    wo_gemm_kernel<<<dim3(T_LEN/128, D_DIM/128), 256, GEMM_SMEM>>>(px, pwor, out);
}